// round 15
// baseline (speedup 1.0000x reference)
#include <cuda_runtime.h>
#include <cuda_bf16.h>
#include <mma.h>
#include <math.h>
#include <stdint.h>

using namespace nvcuda;

// S=40, B=32, T=40, E=256, H=512, V=50000; decoder rows 1248 (pad 1280)
#define NTILES 391

#define CPA16(sdst, gsrc) asm volatile("cp.async.cg.shared.global [%0], [%1], 16;\n" :: "r"(sdst), "l"(gsrc))
#define CPCOMMIT() asm volatile("cp.async.commit_group;\n" ::: "memory")
#define CPWAIT1() asm volatile("cp.async.wait_group 1;\n" ::: "memory")
#define CPWAIT0() asm volatile("cp.async.wait_group 0;\n" ::: "memory")

// ---------------- static device scratch ----------------
__device__ __nv_bfloat16 g_srceb [1280*256];
__device__ __nv_bfloat16 g_srcerb[1280*256];
__device__ __nv_bfloat16 g_tgteb [1280*256];
__device__ __nv_bfloat16 g_wifb  [2048*256];
__device__ __nv_bfloat16 g_wibb  [2048*256];
__device__ __nv_bfloat16 g_widb  [2048*256];
__device__ __nv_bfloat16 g_wattb [512*1024];
__device__ __nv_bfloat16 g_wencb [2*2048*512];   // [dir][2048perm][512]
__device__ __nv_bfloat16 g_wdrb  [2048*1024];    // [2048perm][1024]
__device__ __nv_bfloat16 g_wcombb[512*1536];
__device__ float g_xf   [40*2048*32];   // [t][2048][32]
__device__ float g_xb   [40*2048*32];
__device__ float g_xe   [40*2048*32];
__device__ float g_henc [2*2*512*32];
__device__ __nv_bfloat16 g_hencb[2*2*512*32];
__device__ float g_cenc [2*512*32];
__device__ __nv_bfloat16 g_enchb[1280*1024];
__device__ __nv_bfloat16 g_encpb[1280*512];
__device__ float g_hcc  [32*1024];
__device__ float g_ccc  [32*1024];
__device__ __nv_bfloat16 g_hcatb[2*1024*32];
__device__ float g_cdec [512*32];
__device__ float g_kcat [512*32];
__device__ __nv_bfloat16 g_kcatb[1536*32];
__device__ __nv_bfloat16 g_outsb[1280*512];
__device__ __nv_bfloat16 g_wvb  [50048ull*512];
__device__ float g_pmax [NTILES*1280];
__device__ float g_psum [NTILES*1280];
__device__ float g_pick [1248];
__device__ float g_plogp[1248];
// phase counters (zeroed in k_prep each exec)
__device__ unsigned g_ctr_d;
__device__ unsigned g_ctr_a;
__device__ unsigned g_ctr_c;
__device__ unsigned g_ctr_e;

__device__ __forceinline__ float sigf(float x){ return 1.f/(1.f+expf(-x)); }

__device__ __forceinline__ float fexp(float x){
    float z = fmaxf(x * 1.44269504089f, -100.f);
    float zf = z + 12582912.f;
    int   k  = __float_as_int(zf) - 0x4B400000;
    float r  = z - (zf - 12582912.f);
    float p  = 1.33335581e-3f;
    p = p*r + 9.61812910e-3f;
    p = p*r + 5.55041087e-2f;
    p = p*r + 2.40226507e-1f;
    p = p*r + 6.93147181e-1f;
    p = p*r + 1.0f;
    return __int_as_float(__float_as_int(p) + (k << 23));
}

__device__ __forceinline__ void waitctr(unsigned* c, unsigned tgt){
    if (threadIdx.x == 0){
        while (atomicAdd(c, 0u) < tgt) { }
    }
    __syncthreads();
    __threadfence();
}

// ---------------- prep ----------------
__global__ void k_prep(const float* dWih, const float* dWhh, const float* eWif,
                       const float* eWib, const float* eWhf, const float* eWhb,
                       const float* Watt, const float* Wcomb){
    size_t stride = (size_t)gridDim.x*blockDim.x;
    size_t id0 = (size_t)blockIdx.x*blockDim.x + threadIdx.x;
    if (id0 == 0){ g_ctr_d = 0u; g_ctr_a = 0u; g_ctr_c = 0u; g_ctr_e = 0u; }
    for (size_t i=id0; i<2048ull*1024; i+=stride){
        int r=(int)(i>>10), k=(int)(i&1023);
        int bl=r>>4, loc=r&15, g=loc>>2, jj=loc&3;
        int n = g*512 + bl*4 + jj;
        float v = (k<512) ? dWhh[(size_t)n*512+k] : dWih[(size_t)n*768 + 256 + (k-512)];
        g_wdrb[i] = __float2bfloat16(v);
    }
    for (size_t i=id0; i<2048ull*512; i+=stride){
        int r=(int)(i>>9), k=(int)(i&511);
        int nb=r>>5, loc=r&31, g=loc>>3, jj=loc&7;
        int n = g*512 + nb*8 + jj;
        g_wencb[i]               = __float2bfloat16(eWhf[(size_t)n*512+k]);
        g_wencb[2048ull*512 + i] = __float2bfloat16(eWhb[(size_t)n*512+k]);
    }
    for (size_t i=id0; i<512ull*1536; i+=stride) g_wcombb[i] = __float2bfloat16(Wcomb[i]);
    for (size_t i=id0; i<2048ull*256; i+=stride){
        int n=(int)(i>>8), k=(int)(i&255);
        g_wifb[i] = __float2bfloat16(eWif[i]);
        g_wibb[i] = __float2bfloat16(eWib[i]);
        g_widb[i] = __float2bfloat16(dWih[(size_t)n*768 + k]);
    }
    for (size_t i=id0; i<512ull*1024; i+=stride) g_wattb[i] = __float2bfloat16(Watt[i]);
    for (size_t i=id0; i<2ull*2*512*32; i+=stride){ g_henc[i]=0.f; g_hencb[i]=__float2bfloat16(0.f); }
    for (size_t i=id0; i<2ull*512*32;   i+=stride) g_cenc[i]=0.f;
    for (size_t i=id0; i<512ull*32;     i+=stride) g_cdec[i]=0.f;
    for (size_t i=id0; i<2ull*1024*32;  i+=stride) g_hcatb[i]=__float2bfloat16(0.f);
    for (size_t i=id0; i<32ull*512;     i+=stride) g_outsb[1248ull*512+i]=__float2bfloat16(0.f);
    for (size_t i=id0; i<32ull*256;     i+=stride) g_tgteb[1248ull*256+i]=__float2bfloat16(0.f);
}

__global__ void k_wvb(const float* Wv){
    size_t stride = (size_t)gridDim.x*blockDim.x;
    size_t tot = 50048ull*512/2;
    for (size_t i=(size_t)blockIdx.x*blockDim.x+threadIdx.x; i<tot; i+=stride){
        size_t v = (i*2) >> 9;
        float2 x = (v<50000) ? ((const float2*)Wv)[i] : make_float2(0.f,0.f);
        ((__nv_bfloat162*)g_wvb)[i] = __floats2bfloat162_rn(x.x, x.y);
    }
}

__global__ void k_gather(const int* src, const int* tgt, const float* se, const float* te){
    size_t stride = (size_t)gridDim.x*blockDim.x;
    for (size_t i=(size_t)blockIdx.x*blockDim.x+threadIdx.x; i<(size_t)(1280+1280+1248)*256; i+=stride){
        int k=(int)(i&255); size_t m=i>>8;
        if (m<1280) g_srceb[m*256+k]=__float2bfloat16(se[(size_t)src[m]*256+k]);
        else if (m<2560){
            size_t mm=m-1280; int tt=(int)(mm>>5), bb=(int)(mm&31);
            g_srcerb[mm*256+k]=__float2bfloat16(se[(size_t)src[(39-tt)*32+bb]*256+k]);
        } else {
            size_t mm=m-2560;
            g_tgteb[mm*256+k]=__float2bfloat16(te[(size_t)tgt[mm]*256+k]);
        }
    }
}

// ---------------- 3-stage pipelined bf16 wmma GEMM: C[M][N]=A[M][K]@B[N][K]^T ----------------
// MODE 0: bf16 out | MODE 1: x layout fp32
template<int MODE>
__global__ void __launch_bounds__(256) k_bgemm(const __nv_bfloat16* __restrict__ A,
        const __nv_bfloat16* __restrict__ B, const float* __restrict__ bias,
        float* __restrict__ C, int N, int K){
    extern __shared__ char sm[];
    const int LD = 72;
    __nv_bfloat16* As = (__nv_bfloat16*)sm;
    __nv_bfloat16* Bs = (__nv_bfloat16*)(sm + 3*128*LD*2);
    float* scr = (float*)sm;
    int n0 = blockIdx.x*128, m0 = blockIdx.y*128;
    int tid = threadIdx.x, wp = tid>>5, wm = wp>>2, wn = wp&3;
    wmma::fragment<wmma::matrix_a,16,16,16,__nv_bfloat16,wmma::row_major> af[4];
    wmma::fragment<wmma::matrix_b,16,16,16,__nv_bfloat16,wmma::col_major> bf2[2];
    wmma::fragment<wmma::accumulator,16,16,16,float> cf[4][2];
    #pragma unroll
    for (int i=0;i<4;i++)
        #pragma unroll
        for (int j=0;j<2;j++) wmma::fill_fragment(cf[i][j], 0.f);
    int nch = K>>6;
    int row = tid>>3, seg = tid&7;
    auto issue = [&](int c, int st){
        #pragma unroll
        for (int i=0;i<4;i++){
            int r = row + i*32;
            const __nv_bfloat16* ga = A + (size_t)(m0+r)*K + c*64 + seg*8;
            unsigned sa = (unsigned)__cvta_generic_to_shared(As + (st*128+r)*LD + seg*8);
            CPA16(sa, ga);
            const __nv_bfloat16* gb = B + (size_t)(n0+r)*K + c*64 + seg*8;
            unsigned sb = (unsigned)__cvta_generic_to_shared(Bs + (st*128+r)*LD + seg*8);
            CPA16(sb, gb);
        }
    };
    issue(0,0); CPCOMMIT();
    if (nch > 1){ issue(1,1); CPCOMMIT(); }
    int s3 = 2;
    for (int c=0;c<nch;c++){
        if (c+1<nch) CPWAIT1(); else CPWAIT0();
        __syncthreads();
        if (c+2<nch){ issue(c+2, s3); CPCOMMIT(); s3 = (s3==2)?0:(s3+1); }
        int st = c - (c/3)*3;
        #pragma unroll
        for (int ks=0;ks<4;ks++){
            #pragma unroll
            for (int i=0;i<4;i++)
                wmma::load_matrix_sync(af[i], As + (size_t)(st*128 + wm*64 + i*16)*LD + ks*16, LD);
            #pragma unroll
            for (int j=0;j<2;j++)
                wmma::load_matrix_sync(bf2[j], Bs + (size_t)(st*128 + wn*32 + j*16)*LD + ks*16, LD);
            #pragma unroll
            for (int i=0;i<4;i++)
                #pragma unroll
                for (int j=0;j<2;j++) wmma::mma_sync(cf[i][j], af[i], bf2[j], cf[i][j]);
        }
    }
    __syncthreads();
    #pragma unroll
    for (int i=0;i<4;i++)
        #pragma unroll
        for (int j=0;j<2;j++)
            wmma::store_matrix_sync(&scr[(wm*64+i*16)*132 + wn*32 + j*16], cf[i][j], 132, wmma::mem_row_major);
    __syncthreads();
    if (MODE == 1){
        int mg0 = m0 >> 5;
        #pragma unroll
        for (int it=0; it<16; it++){
            int idx = tid + it*256;
            int g = idx >> 10;
            int n = (idx >> 3) & 127;
            int q = idx & 7;
            float bsv = bias ? bias[n0+n] : 0.f;
            float4 v;
            v.x = scr[(g*32 + q*4 + 0)*132 + n] + bsv;
            v.y = scr[(g*32 + q*4 + 1)*132 + n] + bsv;
            v.z = scr[(g*32 + q*4 + 2)*132 + n] + bsv;
            v.w = scr[(g*32 + q*4 + 3)*132 + n] + bsv;
            *(float4*)&C[(((size_t)(mg0+g))*N + (n0+n))*32 + q*4] = v;
        }
    } else {
        __nv_bfloat16* Cb = (__nv_bfloat16*)C;
        for (int idx=tid; idx<128*128; idx+=256){
            int r=idx>>7, cc=idx&127;
            float v = scr[r*132+cc] + (bias ? bias[n0+cc] : 0.f);
            Cb[(size_t)(m0+r)*N + n0+cc] = __float2bfloat16(v);
        }
    }
}

// ---------------- vocab GEMM + fused lse: 128 threads, 4 warps, 64x64 warp tiles ----------------
__global__ void __launch_bounds__(128) k_vocab(const int* __restrict__ tgt){
    extern __shared__ char sm[];
    const int LD = 72;
    __nv_bfloat16* As = (__nv_bfloat16*)sm;                   // [3][128][72]
    __nv_bfloat16* Bs = (__nv_bfloat16*)(sm + 3*128*LD*2);
    float* scr = (float*)sm;                                   // reuse [128][132]
    int n0 = blockIdx.x*128, m0 = blockIdx.y*128;
    int tid = threadIdx.x, wp = tid>>5, wm = wp>>1, wn = wp&1;
    wmma::fragment<wmma::matrix_a,16,16,16,__nv_bfloat16,wmma::row_major> af[4];
    wmma::fragment<wmma::matrix_b,16,16,16,__nv_bfloat16,wmma::col_major> bf4[4];
    wmma::fragment<wmma::accumulator,16,16,16,float> cf[4][4];
    #pragma unroll
    for (int i=0;i<4;i++)
        #pragma unroll
        for (int j=0;j<4;j++) wmma::fill_fragment(cf[i][j], 0.f);
    auto issue = [&](int c, int st){
        const __nv_bfloat16* ga = g_outsb + (size_t)(m0+tid)*512 + c*64;
        unsigned sa = (unsigned)__cvta_generic_to_shared(As + (st*128+tid)*LD);
        const __nv_bfloat16* gb = g_wvb + (size_t)(n0+tid)*512 + c*64;
        unsigned sb = (unsigned)__cvta_generic_to_shared(Bs + (st*128+tid)*LD);
        #pragma unroll
        for (int s=0;s<8;s++){
            CPA16(sa + s*16, ga + s*8);
            CPA16(sb + s*16, gb + s*8);
        }
    };
    issue(0,0); CPCOMMIT();
    issue(1,1); CPCOMMIT();
    int s3 = 2;
    #pragma unroll 1
    for (int c=0;c<8;c++){
        if (c+1<8) CPWAIT1(); else CPWAIT0();
        __syncthreads();
        if (c+2<8){ issue(c+2, s3); CPCOMMIT(); s3 = (s3==2)?0:(s3+1); }
        int st = c - (c/3)*3;
        #pragma unroll
        for (int ks=0;ks<4;ks++){
            #pragma unroll
            for (int i=0;i<4;i++)
                wmma::load_matrix_sync(af[i], As + (size_t)(st*128 + wm*64 + i*16)*LD + ks*16, LD);
            #pragma unroll
            for (int j=0;j<4;j++)
                wmma::load_matrix_sync(bf4[j], Bs + (size_t)(st*128 + wn*64 + j*16)*LD + ks*16, LD);
            #pragma unroll
            for (int i=0;i<4;i++)
                #pragma unroll
                for (int j=0;j<4;j++) wmma::mma_sync(cf[i][j], af[i], bf4[j], cf[i][j]);
        }
    }
    __syncthreads();
    #pragma unroll
    for (int i=0;i<4;i++)
        #pragma unroll
        for (int j=0;j<4;j++)
            wmma::store_matrix_sync(&scr[(wm*64+i*16)*132 + wn*64 + j*16], cf[i][j], 132, wmma::mem_row_major);
    __syncthreads();
    {
        int m = m0 + tid;
        if (m < 1248){
            int valid = min(128, 50000 - n0);
            int tv = tgt[m + 32];
            int lv = tv - n0;
            float mx = -INFINITY;
            for (int cc=0; cc<valid; cc++) mx = fmaxf(mx, scr[tid*132+cc]);
            float s = 0.f;
            for (int cc=0; cc<valid; cc++) s += fexp(scr[tid*132+cc]-mx);
            g_pmax[(size_t)blockIdx.x*1280 + m] = mx;
            g_psum[(size_t)blockIdx.x*1280 + m] = s;
            if (lv >= 0 && lv < valid) g_pick[m] = scr[tid*132 + lv];
        }
    }
}

// ---------------- fp32 GEMM transposed-out (decoder init projections) ----------------
__global__ void __launch_bounds__(256) k_gemm(const float* A, int lda, const float* W, int ldw,
        float* C, __nv_bfloat16* Cb, int M, int N, int K){
    int m0 = blockIdx.x*64, n0 = blockIdx.y*64;
    int tid = threadIdx.x, tx = tid&15, ty = tid>>4;
    __shared__ float As[64][33], Bs[64][33];
    float acc[4][4] = {};
    for (int k0=0;k0<K;k0+=32){
        #pragma unroll
        for (int p=0;p<8;p++){
            int idx=tid+p*256; int r=idx>>5, kk=idx&31;
            As[r][kk] = (m0+r<M) ? A[(size_t)(m0+r)*lda+k0+kk] : 0.f;
            Bs[r][kk] = (n0+r<N) ? W[(size_t)(n0+r)*ldw+k0+kk] : 0.f;
        }
        __syncthreads();
        #pragma unroll
        for (int kk=0;kk<32;kk++){
            float av[4], bv[4];
            #pragma unroll
            for (int i=0;i<4;i++) av[i]=As[ty*4+i][kk];
            #pragma unroll
            for (int j=0;j<4;j++) bv[j]=Bs[tx*4+j][kk];
            #pragma unroll
            for (int i=0;i<4;i++)
                #pragma unroll
                for (int j=0;j<4;j++) acc[i][j]+=av[i]*bv[j];
        }
        __syncthreads();
    }
    #pragma unroll
    for (int i=0;i<4;i++){
        int m=m0+ty*4+i; if (m>=M) continue;
        #pragma unroll
        for (int j=0;j<4;j++){
            int n=n0+tx*4+j; if (n>=N) continue;
            if (C)  C [(size_t)n*32 + m] = acc[i][j];
            if (Cb) Cb[(size_t)n*32 + m] = __float2bfloat16(acc[i][j]);
        }
    }
}

// ---------------- persistent encoder: 128 blocks, 40 steps, counter barrier ----------------
__global__ void __launch_bounds__(256,2) k_enc_all(){
    __shared__ float Rs[8][32][32];
    int blk = blockIdx.x, tid = threadIdx.x, w = tid>>5;
    int dir = blk>>6, nb = blk&63;
    const __nv_bfloat16* Aw = g_wencb + ((size_t)dir*2048 + nb*32)*512;
    for (int t=0;t<40;t++){
        int par = t&1;
        const __nv_bfloat16* Bh = g_hencb + (size_t)(par*2+dir)*512*32;
        wmma::fragment<wmma::matrix_a,16,16,16,__nv_bfloat16,wmma::row_major> af[2];
        wmma::fragment<wmma::matrix_b,16,16,16,__nv_bfloat16,wmma::row_major> bf;
        wmma::fragment<wmma::accumulator,16,16,16,float> cf[2][2];
        #pragma unroll
        for (int i=0;i<2;i++)
            #pragma unroll
            for (int j=0;j<2;j++) wmma::fill_fragment(cf[i][j], 0.f);
        #pragma unroll
        for (int kt=0;kt<4;kt++){
            int k = w*64 + kt*16;
            #pragma unroll
            for (int mi=0;mi<2;mi++) wmma::load_matrix_sync(af[mi], Aw + (size_t)mi*16*512 + k, 512);
            #pragma unroll
            for (int ni=0;ni<2;ni++){
                wmma::load_matrix_sync(bf, Bh + (size_t)k*32 + ni*16, 32);
                #pragma unroll
                for (int mi=0;mi<2;mi++) wmma::mma_sync(cf[mi][ni], af[mi], bf, cf[mi][ni]);
            }
        }
        #pragma unroll
        for (int mi=0;mi<2;mi++)
            #pragma unroll
            for (int ni=0;ni<2;ni++)
                wmma::store_matrix_sync(&Rs[w][mi*16][ni*16], cf[mi][ni], 32, wmma::mem_row_major);
        __syncthreads();
        {
            int jj = tid>>5, b = tid&31;
            float gg[4];
            #pragma unroll
            for (int g=0; g<4; g++){
                float s = 0.f;
                #pragma unroll
                for (int w8=0; w8<8; w8++) s += Rs[w8][g*8+jj][b];
                gg[g] = s;
            }
            int j = nb*8 + jj;
            const float* xr = (dir?g_xb:g_xf) + (size_t)t*2048*32;
            float gi = sigf (gg[0] + xr[(size_t)(      j)*32+b]);
            float gf = sigf (gg[1] + xr[(size_t)( 512+j)*32+b]);
            float gc = tanhf(gg[2] + xr[(size_t)(1024+j)*32+b]);
            float go = sigf (gg[3] + xr[(size_t)(1536+j)*32+b]);
            size_t ci = ((size_t)dir*512+j)*32+b;
            float cn = gf*g_cenc[ci] + gi*gc;
            g_cenc[ci] = cn;
            float hn = go*tanhf(cn);
            size_t ho = (((size_t)(1-par)*2+dir)*512 + j)*32 + b;
            g_henc[ho]  = hn;
            g_hencb[ho] = __float2bfloat16(hn);
            int s = dir ? (39-t) : t;
            g_enchb[((size_t)b*40+s)*1024 + dir*512 + j] = __float2bfloat16(hn);
        }
        __threadfence();
        __syncthreads();
        if (tid == 0) atomicAdd(&g_ctr_e, 1u);
        if (t < 39) waitctr(&g_ctr_e, (unsigned)(t+1)*128u);
    }
}

__global__ void k_mkcat(){
    int i = blockIdx.x*blockDim.x + threadIdx.x;
    if (i < 32*1024){
        int b = i>>10, k = i&1023; int dir = k>>9, kk = k&511;
        g_hcc[i] = g_henc[(((size_t)0*2+dir)*512 + kk)*32 + b];
        g_ccc[i] = g_cenc[((size_t)dir*512 + kk)*32 + b];
    }
}

// ---------------- persistent fused decoder: 224 blocks, 39 steps ----------------
__global__ void __launch_bounds__(256,2) k_ddec(const float* __restrict__ masks){
    __shared__ float Rs[8][16][32];
    int blk = blockIdx.x, tid = threadIdx.x, w = tid>>5;
    for (int t=0;t<39;t++){
        int par = t&1;
        if (blk < 128){
            if (t > 0){
                waitctr(&g_ctr_d, (unsigned)t*128u);
                waitctr(&g_ctr_c, (unsigned)t*32u);
            }
            int bl = blk;
            const __nv_bfloat16* Aw = g_wdrb + (size_t)bl*16*1024;
            const __nv_bfloat16* Bh = g_hcatb + (size_t)par*1024*32;
            wmma::fragment<wmma::matrix_a,16,16,16,__nv_bfloat16,wmma::row_major> af;
            wmma::fragment<wmma::matrix_b,16,16,16,__nv_bfloat16,wmma::row_major> bf;
            wmma::fragment<wmma::accumulator,16,16,16,float> cf[2];
            #pragma unroll
            for (int j=0;j<2;j++) wmma::fill_fragment(cf[j], 0.f);
            #pragma unroll
            for (int ktl=0;ktl<8;ktl++){
                int k = (w*8 + ktl)*16;
                wmma::load_matrix_sync(af, Aw + k, 1024);
                #pragma unroll
                for (int ni=0;ni<2;ni++){
                    wmma::load_matrix_sync(bf, Bh + (size_t)k*32 + ni*16, 32);
                    wmma::mma_sync(cf[ni], af, bf, cf[ni]);
                }
            }
            #pragma unroll
            for (int ni=0;ni<2;ni++)
                wmma::store_matrix_sync(&Rs[w][0][ni*16], cf[ni], 32, wmma::mem_row_major);
            __syncthreads();
            if (tid < 128){
                int jj = tid>>5, b = tid&31;
                float gg[4];
                #pragma unroll
                for (int g=0; g<4; g++){
                    float s = 0.f;
                    #pragma unroll
                    for (int w8=0; w8<8; w8++) s += Rs[w8][g*4+jj][b];
                    gg[g] = s;
                }
                int j = bl*4 + jj;
                const float* xr = g_xe + (size_t)t*2048*32;
                float gi = sigf (gg[0] + xr[(size_t)(      j)*32+b]);
                float gf = sigf (gg[1] + xr[(size_t)( 512+j)*32+b]);
                float gc = tanhf(gg[2] + xr[(size_t)(1024+j)*32+b]);
                float go = sigf (gg[3] + xr[(size_t)(1536+j)*32+b]);
                size_t ci = (size_t)j*32 + b;
                float cn = gf*g_cdec[ci] + gi*gc;
                g_cdec[ci] = cn;
                float hn = go*tanhf(cn);
                __nv_bfloat16 hb = __float2bfloat16(hn);
                g_kcat[ci] = hn;
                g_kcatb[ci] = hb;
                g_hcatb[(size_t)(1-par)*1024*32 + ci] = hb;
            }
            __threadfence();
            __syncthreads();
            if (tid == 0) atomicAdd(&g_ctr_d, 1u);
        } else if (blk < 192){
            int ab = blk - 128, b = ab>>1, half = ab&1;
            int lane = tid&31;
            float* hv = (float*)Rs;
            float* sc = hv + 512;
            waitctr(&g_ctr_d, (unsigned)(t+1)*128u);
            for (int i=tid;i<512;i+=256) hv[i] = g_kcat[(size_t)i*32+b];
            __syncthreads();
            #pragma unroll
            for (int q=0;q<5;q++){
                int s = w*5+q;
                const __nv_bfloat16* ep = g_encpb + ((size_t)b*40+s)*512;
                float p = 0.f;
                for (int k=lane;k<512;k+=32) p += __bfloat162float(ep[k])*hv[k];
                #pragma unroll
                for (int o=16;o;o>>=1) p += __shfl_down_sync(0xffffffffu, p, o);
                if (!lane) sc[s] = (masks[b*40+s] > 0.f) ? -INFINITY : p;
            }
            __syncthreads();
            if (tid == 0){
                float m = -INFINITY;
                for (int s=0;s<40;s++) m = fmaxf(m, sc[s]);
                float sum = 0.f;
                for (int s=0;s<40;s++){ float e = expf(sc[s]-m); sc[s]=e; sum+=e; }
                float inv = 1.f/sum;
                for (int s=0;s<40;s++) sc[s] *= inv;
            }
            __syncthreads();
            for (int jj=tid + half*512; jj<half*512+512; jj+=256){
                float acc = 0.f;
                #pragma unroll 8
                for (int s=0;s<40;s++)
                    acc += sc[s]*__bfloat162float(g_enchb[((size_t)b*40+s)*1024 + jj]);
                g_kcatb[(size_t)(512+jj)*32 + b] = __float2bfloat16(acc);
            }
            __threadfence();
            __syncthreads();
            if (tid == 0) atomicAdd(&g_ctr_a, 1u);
        } else {
            int bl = blk - 192;
            const __nv_bfloat16* Aw = g_wcombb + (size_t)bl*16*1536;
            wmma::fragment<wmma::matrix_a,16,16,16,__nv_bfloat16,wmma::row_major> af;
            wmma::fragment<wmma::matrix_b,16,16,16,__nv_bfloat16,wmma::row_major> bf;
            wmma::fragment<wmma::accumulator,16,16,16,float> cf[2];
            #pragma unroll
            for (int j=0;j<2;j++) wmma::fill_fragment(cf[j], 0.f);
            waitctr(&g_ctr_d, (unsigned)(t+1)*128u);
            #pragma unroll
            for (int i=0;i<4;i++){
                int k = (w + 8*i)*16;
                wmma::load_matrix_sync(af, Aw + k, 1536);
                #pragma unroll
                for (int ni=0;ni<2;ni++){
                    wmma::load_matrix_sync(bf, g_kcatb + (size_t)k*32 + ni*16, 32);
                    wmma::mma_sync(cf[ni], af, bf, cf[ni]);
                }
            }
            waitctr(&g_ctr_a, (unsigned)(t+1)*64u);
            #pragma unroll
            for (int i=4;i<12;i++){
                int k = (w + 8*i)*16;
                wmma::load_matrix_sync(af, Aw + k, 1536);
                #pragma unroll
                for (int ni=0;ni<2;ni++){
                    wmma::load_matrix_sync(bf, g_kcatb + (size_t)k*32 + ni*16, 32);
                    wmma::mma_sync(cf[ni], af, bf, cf[ni]);
                }
            }
            #pragma unroll
            for (int ni=0;ni<2;ni++)
                wmma::store_matrix_sync(&Rs[w][0][ni*16], cf[ni], 32, wmma::mem_row_major);
            __syncthreads();
            #pragma unroll
            for (int rep=0; rep<2; rep++){
                int idx = tid + rep*256;
                int nloc = idx>>5, b = idx&31;
                float s = 0.f;
                #pragma unroll
                for (int w8=0; w8<8; w8++) s += Rs[w8][nloc][b];
                float v = tanhf(s);
                int n = bl*16 + nloc;
                g_hcatb[(size_t)(1-par)*1024*32 + (size_t)(512+n)*32 + b] = __float2bfloat16(v);
                g_outsb[((size_t)t*32+b)*512 + n] = __float2bfloat16(v);
            }
            __threadfence();
            __syncthreads();
            if (tid == 0) atomicAdd(&g_ctr_c, 1u);
        }
    }
}

// ---------------- final lse combine + output ----------------
__global__ void k_lse(const int* tgt){
    int m = blockIdx.x*blockDim.x + threadIdx.x;
    if (m >= 1248) return;
    float mx = -INFINITY, s = 0.f;
    for (int j=0;j<NTILES;j++){
        float pm = g_pmax[(size_t)j*1280 + m], ps = g_psum[(size_t)j*1280 + m];
        if (pm > mx){ s = s*fexp(mx-pm) + ps; mx = pm; }
        else s += ps*fexp(pm-mx);
    }
    float lse = mx + logf(s);
    int tv = tgt[m + 32];
    g_plogp[m] = (tv != 0) ? (g_pick[m] - lse) : 0.f;
}

__global__ void k_out(float* out){
    int b = threadIdx.x;
    if (b < 32){
        float s = 0.f;
        for (int t=0;t<39;t++) s += g_plogp[t*32 + b];
        out[b] = s;
    }
}

// ---------------- launch ----------------
extern "C" void kernel_launch(void* const* d_in, const int* in_sizes, int n_in,
                              void* d_out, int out_size){
    const int*   src   = (const int*)d_in[0];
    const int*   tgt   = (const int*)d_in[1];
    const float* masks = (const float*)d_in[2];
    const float* se    = (const float*)d_in[3];
    const float* te    = (const float*)d_in[4];
    const float* eWif  = (const float*)d_in[5];
    const float* eWhf  = (const float*)d_in[6];
    const float* ebf   = (const float*)d_in[7];
    const float* eWib  = (const float*)d_in[8];
    const float* eWhb  = (const float*)d_in[9];
    const float* ebb   = (const float*)d_in[10];
    const float* dWih  = (const float*)d_in[11];
    const float* dWhh  = (const float*)d_in[12];
    const float* db    = (const float*)d_in[13];
    const float* Wh    = (const float*)d_in[14];
    const float* Wc    = (const float*)d_in[15];
    const float* Watt  = (const float*)d_in[16];
    const float* Wcomb = (const float*)d_in[17];
    const float* Wv    = (const float*)d_in[18];

    __nv_bfloat16 *p_srceb,*p_srcerb,*p_tgteb,*p_wifb,*p_wibb,*p_widb,*p_wattb,*p_enchb,*p_wvb,*p_outsb,*p_hcatb,*p_encpb;
    float *p_xf,*p_xb,*p_xe,*p_hcc,*p_ccc,*p_cdec;
    cudaGetSymbolAddress((void**)&p_srceb,  g_srceb);
    cudaGetSymbolAddress((void**)&p_srcerb, g_srcerb);
    cudaGetSymbolAddress((void**)&p_tgteb,  g_tgteb);
    cudaGetSymbolAddress((void**)&p_wifb,   g_wifb);
    cudaGetSymbolAddress((void**)&p_wibb,   g_wibb);
    cudaGetSymbolAddress((void**)&p_widb,   g_widb);
    cudaGetSymbolAddress((void**)&p_wattb,  g_wattb);
    cudaGetSymbolAddress((void**)&p_enchb,  g_enchb);
    cudaGetSymbolAddress((void**)&p_wvb,    g_wvb);
    cudaGetSymbolAddress((void**)&p_outsb,  g_outsb);
    cudaGetSymbolAddress((void**)&p_hcatb,  g_hcatb);
    cudaGetSymbolAddress((void**)&p_encpb,  g_encpb);
    cudaGetSymbolAddress((void**)&p_xf,     g_xf);
    cudaGetSymbolAddress((void**)&p_xb,     g_xb);
    cudaGetSymbolAddress((void**)&p_xe,     g_xe);
    cudaGetSymbolAddress((void**)&p_hcc,    g_hcc);
    cudaGetSymbolAddress((void**)&p_ccc,    g_ccc);
    cudaGetSymbolAddress((void**)&p_cdec,   g_cdec);

    const int SM_GEMM = 3*2*128*72*2;   // 110592
    cudaFuncSetAttribute(k_bgemm<0>, cudaFuncAttributeMaxDynamicSharedMemorySize, SM_GEMM);
    cudaFuncSetAttribute(k_bgemm<1>, cudaFuncAttributeMaxDynamicSharedMemorySize, SM_GEMM);
    cudaFuncSetAttribute(k_vocab,    cudaFuncAttributeMaxDynamicSharedMemorySize, SM_GEMM);

    k_gather<<<512,256>>>(src, tgt, se, te);
    k_prep<<<1024,256>>>(dWih, dWhh, eWif, eWib, eWhf, eWhb, Watt, Wcomb);
    k_wvb<<<2048,256>>>(Wv);
    k_bgemm<1><<<dim3(16,10),256,SM_GEMM>>>(p_srceb,  p_wifb, ebf, p_xf, 2048, 256);
    k_bgemm<1><<<dim3(16,10),256,SM_GEMM>>>(p_srcerb, p_wibb, ebb, p_xb, 2048, 256);

    k_enc_all<<<128,256>>>();

    k_bgemm<1><<<dim3(16,10),256,SM_GEMM>>>(p_tgteb, p_widb, db, p_xe, 2048, 256);

    k_mkcat<<<128,256>>>();
    k_gemm<<<dim3(1,8),256>>>(p_hcc, 1024, Wh, 1024, nullptr, p_hcatb, 32, 512, 1024);
    k_gemm<<<dim3(1,8),256>>>(p_ccc, 1024, Wc, 1024, p_cdec, nullptr, 32, 512, 1024);
    k_bgemm<0><<<dim3(4,10),256,SM_GEMM>>>(p_enchb, p_wattb, nullptr, (float*)p_encpb, 512, 1024);

    k_ddec<<<224,256>>>(masks);

    k_vocab<<<dim3(NTILES,10),128,SM_GEMM>>>(tgt);
    k_lse<<<10,128>>>(tgt);
    k_out<<<1,32>>>((float*)d_out);
}

// round 16
// speedup vs baseline: 1.1046x; 1.1046x over previous
#include <cuda_runtime.h>
#include <cuda_bf16.h>
#include <mma.h>
#include <math.h>
#include <stdint.h>

using namespace nvcuda;

// S=40, B=32, T=40, E=256, H=512, V=50000; decoder rows 1248 (pad 1280)
#define NTILES 391

#define CPA16(sdst, gsrc) asm volatile("cp.async.cg.shared.global [%0], [%1], 16;\n" :: "r"(sdst), "l"(gsrc))
#define CPCOMMIT() asm volatile("cp.async.commit_group;\n" ::: "memory")
#define CPWAIT1() asm volatile("cp.async.wait_group 1;\n" ::: "memory")
#define CPWAIT0() asm volatile("cp.async.wait_group 0;\n" ::: "memory")

// ---------------- static device scratch ----------------
__device__ __nv_bfloat16 g_srceb [1280*256];
__device__ __nv_bfloat16 g_srcerb[1280*256];
__device__ __nv_bfloat16 g_tgteb [1280*256];
__device__ __nv_bfloat16 g_wifb  [2048*256];
__device__ __nv_bfloat16 g_wibb  [2048*256];
__device__ __nv_bfloat16 g_widb  [2048*256];
__device__ __nv_bfloat16 g_wattb [512*1024];
__device__ __nv_bfloat16 g_wencb [2*2048*512];   // [dir][2048perm][512]
__device__ __nv_bfloat16 g_wdrb  [2048*1024];    // [2048perm][1024]
__device__ __nv_bfloat16 g_wcombb[512*1536];
__device__ float g_xf   [40*2048*32];   // [t][2048][32]
__device__ float g_xb   [40*2048*32];
__device__ float g_xe   [40*2048*32];
__device__ float g_henc [2*2*512*32];
__device__ __nv_bfloat16 g_hencb[2*2*512*32];
__device__ float g_cenc [2*512*32];
__device__ __nv_bfloat16 g_enchb[1280*1024];
__device__ __nv_bfloat16 g_encpb[1280*512];
__device__ float g_hcc  [32*1024];
__device__ float g_ccc  [32*1024];
__device__ __nv_bfloat16 g_hcatb[2*1024*32];
__device__ float g_cdec [512*32];
__device__ float g_kcat [512*32];
__device__ __nv_bfloat16 g_kcatb[1536*32];
__device__ __nv_bfloat16 g_outsb[1280*512];
__device__ __nv_bfloat16 g_wvb  [50048ull*512];
__device__ float g_pmax [NTILES*1280];
__device__ float g_psum [NTILES*1280];
__device__ float g_pick [1248];
__device__ float g_plogp[1248];
// phase counters (zeroed in k_prep each exec)
__device__ unsigned g_ctr_d;
__device__ unsigned g_ctr_a;
__device__ unsigned g_ctr_c;
__device__ unsigned g_ctr_e;

__device__ __forceinline__ float sigf(float x){ return 1.f/(1.f+expf(-x)); }

__device__ __forceinline__ float fexp(float x){
    float z = fmaxf(x * 1.44269504089f, -100.f);
    float zf = z + 12582912.f;
    int   k  = __float_as_int(zf) - 0x4B400000;
    float r  = z - (zf - 12582912.f);
    float p  = 1.33335581e-3f;
    p = p*r + 9.61812910e-3f;
    p = p*r + 5.55041087e-2f;
    p = p*r + 2.40226507e-1f;
    p = p*r + 6.93147181e-1f;
    p = p*r + 1.0f;
    return __int_as_float(__float_as_int(p) + (k << 23));
}

__device__ __forceinline__ void waitctr(unsigned* c, unsigned tgt){
    if (threadIdx.x == 0){
        while (atomicAdd(c, 0u) < tgt) { }
    }
    __syncthreads();
    __threadfence();
}

// ---------------- prep ----------------
__global__ void k_prep(const float* dWih, const float* dWhh, const float* eWif,
                       const float* eWib, const float* eWhf, const float* eWhb,
                       const float* Watt, const float* Wcomb){
    size_t stride = (size_t)gridDim.x*blockDim.x;
    size_t id0 = (size_t)blockIdx.x*blockDim.x + threadIdx.x;
    if (id0 == 0){ g_ctr_d = 0u; g_ctr_a = 0u; g_ctr_c = 0u; g_ctr_e = 0u; }
    for (size_t i=id0; i<2048ull*1024; i+=stride){
        int r=(int)(i>>10), k=(int)(i&1023);
        int bl=r>>4, loc=r&15, g=loc>>2, jj=loc&3;
        int n = g*512 + bl*4 + jj;
        float v = (k<512) ? dWhh[(size_t)n*512+k] : dWih[(size_t)n*768 + 256 + (k-512)];
        g_wdrb[i] = __float2bfloat16(v);
    }
    for (size_t i=id0; i<2048ull*512; i+=stride){
        int r=(int)(i>>9), k=(int)(i&511);
        int nb=r>>5, loc=r&31, g=loc>>3, jj=loc&7;
        int n = g*512 + nb*8 + jj;
        g_wencb[i]               = __float2bfloat16(eWhf[(size_t)n*512+k]);
        g_wencb[2048ull*512 + i] = __float2bfloat16(eWhb[(size_t)n*512+k]);
    }
    for (size_t i=id0; i<512ull*1536; i+=stride) g_wcombb[i] = __float2bfloat16(Wcomb[i]);
    for (size_t i=id0; i<2048ull*256; i+=stride){
        int n=(int)(i>>8), k=(int)(i&255);
        g_wifb[i] = __float2bfloat16(eWif[i]);
        g_wibb[i] = __float2bfloat16(eWib[i]);
        g_widb[i] = __float2bfloat16(dWih[(size_t)n*768 + k]);
    }
    for (size_t i=id0; i<512ull*1024; i+=stride) g_wattb[i] = __float2bfloat16(Watt[i]);
    for (size_t i=id0; i<2ull*2*512*32; i+=stride){ g_henc[i]=0.f; g_hencb[i]=__float2bfloat16(0.f); }
    for (size_t i=id0; i<2ull*512*32;   i+=stride) g_cenc[i]=0.f;
    for (size_t i=id0; i<512ull*32;     i+=stride) g_cdec[i]=0.f;
    for (size_t i=id0; i<2ull*1024*32;  i+=stride) g_hcatb[i]=__float2bfloat16(0.f);
    for (size_t i=id0; i<32ull*512;     i+=stride) g_outsb[1248ull*512+i]=__float2bfloat16(0.f);
    for (size_t i=id0; i<32ull*256;     i+=stride) g_tgteb[1248ull*256+i]=__float2bfloat16(0.f);
}

__global__ void k_wvb(const float* Wv){
    size_t stride = (size_t)gridDim.x*blockDim.x;
    size_t tot = 50048ull*512/2;
    for (size_t i=(size_t)blockIdx.x*blockDim.x+threadIdx.x; i<tot; i+=stride){
        size_t v = (i*2) >> 9;
        float2 x = (v<50000) ? ((const float2*)Wv)[i] : make_float2(0.f,0.f);
        ((__nv_bfloat162*)g_wvb)[i] = __floats2bfloat162_rn(x.x, x.y);
    }
}

__global__ void k_gather(const int* src, const int* tgt, const float* se, const float* te){
    size_t stride = (size_t)gridDim.x*blockDim.x;
    for (size_t i=(size_t)blockIdx.x*blockDim.x+threadIdx.x; i<(size_t)(1280+1280+1248)*256; i+=stride){
        int k=(int)(i&255); size_t m=i>>8;
        if (m<1280) g_srceb[m*256+k]=__float2bfloat16(se[(size_t)src[m]*256+k]);
        else if (m<2560){
            size_t mm=m-1280; int tt=(int)(mm>>5), bb=(int)(mm&31);
            g_srcerb[mm*256+k]=__float2bfloat16(se[(size_t)src[(39-tt)*32+bb]*256+k]);
        } else {
            size_t mm=m-2560;
            g_tgteb[mm*256+k]=__float2bfloat16(te[(size_t)tgt[mm]*256+k]);
        }
    }
}

// ---------------- 3-stage pipelined bf16 wmma GEMM: C[M][N]=A[M][K]@B[N][K]^T ----------------
// MODE 0: bf16 out | MODE 1: x layout fp32 | MODE 2: vocab lse partials
template<int MODE>
__global__ void __launch_bounds__(256) k_bgemm(const __nv_bfloat16* __restrict__ A,
        const __nv_bfloat16* __restrict__ B, const float* __restrict__ bias,
        float* __restrict__ C, int N, int K, const int* __restrict__ tgt){
    extern __shared__ char sm[];
    const int LD = 72;
    __nv_bfloat16* As = (__nv_bfloat16*)sm;
    __nv_bfloat16* Bs = (__nv_bfloat16*)(sm + 3*128*LD*2);
    float* scr = (float*)sm;
    int n0 = blockIdx.x*128, m0 = blockIdx.y*128;
    int tid = threadIdx.x, wp = tid>>5, wm = wp>>2, wn = wp&3;
    wmma::fragment<wmma::matrix_a,16,16,16,__nv_bfloat16,wmma::row_major> af[4];
    wmma::fragment<wmma::matrix_b,16,16,16,__nv_bfloat16,wmma::col_major> bf2[2];
    wmma::fragment<wmma::accumulator,16,16,16,float> cf[4][2];
    #pragma unroll
    for (int i=0;i<4;i++)
        #pragma unroll
        for (int j=0;j<2;j++) wmma::fill_fragment(cf[i][j], 0.f);
    int nch = K>>6;
    int row = tid>>3, seg = tid&7;
    auto issue = [&](int c, int st){
        #pragma unroll
        for (int i=0;i<4;i++){
            int r = row + i*32;
            const __nv_bfloat16* ga = A + (size_t)(m0+r)*K + c*64 + seg*8;
            unsigned sa = (unsigned)__cvta_generic_to_shared(As + (st*128+r)*LD + seg*8);
            CPA16(sa, ga);
            const __nv_bfloat16* gb = B + (size_t)(n0+r)*K + c*64 + seg*8;
            unsigned sb = (unsigned)__cvta_generic_to_shared(Bs + (st*128+r)*LD + seg*8);
            CPA16(sb, gb);
        }
    };
    issue(0,0); CPCOMMIT();
    if (nch > 1){ issue(1,1); CPCOMMIT(); }
    int s3 = 2;
    for (int c=0;c<nch;c++){
        if (c+1<nch) CPWAIT1(); else CPWAIT0();
        __syncthreads();
        if (c+2<nch){ issue(c+2, s3); CPCOMMIT(); s3 = (s3==2)?0:(s3+1); }
        int st = c - (c/3)*3;
        #pragma unroll
        for (int ks=0;ks<4;ks++){
            #pragma unroll
            for (int i=0;i<4;i++)
                wmma::load_matrix_sync(af[i], As + (size_t)(st*128 + wm*64 + i*16)*LD + ks*16, LD);
            #pragma unroll
            for (int j=0;j<2;j++)
                wmma::load_matrix_sync(bf2[j], Bs + (size_t)(st*128 + wn*32 + j*16)*LD + ks*16, LD);
            #pragma unroll
            for (int i=0;i<4;i++)
                #pragma unroll
                for (int j=0;j<2;j++) wmma::mma_sync(cf[i][j], af[i], bf2[j], cf[i][j]);
        }
    }
    __syncthreads();
    #pragma unroll
    for (int i=0;i<4;i++)
        #pragma unroll
        for (int j=0;j<2;j++)
            wmma::store_matrix_sync(&scr[(wm*64+i*16)*132 + wn*32 + j*16], cf[i][j], 132, wmma::mem_row_major);
    __syncthreads();
    if (MODE == 2){
        int r = tid>>1, hh = tid&1;
        int m = m0 + r;
        if (m < 1248){
            int valid = min(128, 50000 - n0);
            int c0 = hh*64, c1 = min(c0+64, valid);
            float mx = -INFINITY, s = 0.f;
            for (int cc=c0; cc<c1; cc++) mx = fmaxf(mx, scr[r*132+cc]);
            for (int cc=c0; cc<c1; cc++) s += fexp(scr[r*132+cc]-mx);
            float mo = __shfl_xor_sync(0xffffffffu, mx, 1);
            float so = __shfl_xor_sync(0xffffffffu, s, 1);
            float M = fmaxf(mx, mo);
            float S = ((mx == -INFINITY) ? 0.f : s*fexp(mx-M)) +
                      ((mo == -INFINITY) ? 0.f : so*fexp(mo-M));
            if (hh == 0){
                g_pmax[(size_t)blockIdx.x*1280 + m] = M;
                g_psum[(size_t)blockIdx.x*1280 + m] = S;
            }
            int tv = tgt[m + 32];
            int lv = tv - n0;
            if (lv >= c0 && lv < c1) g_pick[m] = scr[r*132 + lv];
        }
    } else if (MODE == 1){
        int mg0 = m0 >> 5;
        #pragma unroll
        for (int it=0; it<16; it++){
            int idx = tid + it*256;
            int g = idx >> 10;
            int n = (idx >> 3) & 127;
            int q = idx & 7;
            float bsv = bias ? bias[n0+n] : 0.f;
            float4 v;
            v.x = scr[(g*32 + q*4 + 0)*132 + n] + bsv;
            v.y = scr[(g*32 + q*4 + 1)*132 + n] + bsv;
            v.z = scr[(g*32 + q*4 + 2)*132 + n] + bsv;
            v.w = scr[(g*32 + q*4 + 3)*132 + n] + bsv;
            *(float4*)&C[(((size_t)(mg0+g))*N + (n0+n))*32 + q*4] = v;
        }
    } else {
        __nv_bfloat16* Cb = (__nv_bfloat16*)C;
        for (int idx=tid; idx<128*128; idx+=256){
            int r=idx>>7, cc=idx&127;
            float v = scr[r*132+cc] + (bias ? bias[n0+cc] : 0.f);
            Cb[(size_t)(m0+r)*N + n0+cc] = __float2bfloat16(v);
        }
    }
}

// ---------------- fp32 GEMM transposed-out (decoder init projections) ----------------
__global__ void __launch_bounds__(256) k_gemm(const float* A, int lda, const float* W, int ldw,
        float* C, __nv_bfloat16* Cb, int M, int N, int K){
    int m0 = blockIdx.x*64, n0 = blockIdx.y*64;
    int tid = threadIdx.x, tx = tid&15, ty = tid>>4;
    __shared__ float As[64][33], Bs[64][33];
    float acc[4][4] = {};
    for (int k0=0;k0<K;k0+=32){
        #pragma unroll
        for (int p=0;p<8;p++){
            int idx=tid+p*256; int r=idx>>5, kk=idx&31;
            As[r][kk] = (m0+r<M) ? A[(size_t)(m0+r)*lda+k0+kk] : 0.f;
            Bs[r][kk] = (n0+r<N) ? W[(size_t)(n0+r)*ldw+k0+kk] : 0.f;
        }
        __syncthreads();
        #pragma unroll
        for (int kk=0;kk<32;kk++){
            float av[4], bv[4];
            #pragma unroll
            for (int i=0;i<4;i++) av[i]=As[ty*4+i][kk];
            #pragma unroll
            for (int j=0;j<4;j++) bv[j]=Bs[tx*4+j][kk];
            #pragma unroll
            for (int i=0;i<4;i++)
                #pragma unroll
                for (int j=0;j<4;j++) acc[i][j]+=av[i]*bv[j];
        }
        __syncthreads();
    }
    #pragma unroll
    for (int i=0;i<4;i++){
        int m=m0+ty*4+i; if (m>=M) continue;
        #pragma unroll
        for (int j=0;j<4;j++){
            int n=n0+tx*4+j; if (n>=N) continue;
            if (C)  C [(size_t)n*32 + m] = acc[i][j];
            if (Cb) Cb[(size_t)n*32 + m] = __float2bfloat16(acc[i][j]);
        }
    }
}

// ---------------- persistent encoder: 128 blocks, 40 steps, counter barrier ----------------
__global__ void __launch_bounds__(256,2) k_enc_all(){
    __shared__ float Rs[8][32][32];
    int blk = blockIdx.x, tid = threadIdx.x, w = tid>>5;
    int dir = blk>>6, nb = blk&63;
    const __nv_bfloat16* Aw = g_wencb + ((size_t)dir*2048 + nb*32)*512;
    int jj0 = tid>>5, b0 = tid&31;
    int j0 = nb*8 + jj0;
    const float* xbase = dir ? g_xb : g_xf;
    for (int t=0;t<40;t++){
        int par = t&1;
        const __nv_bfloat16* Bh = g_hencb + (size_t)(par*2+dir)*512*32;
        // prefetch x gate operands (overlaps the wmma mainloop)
        const float* xr = xbase + (size_t)t*2048*32;
        float x0 = xr[(size_t)(      j0)*32+b0];
        float x1 = xr[(size_t)( 512+j0)*32+b0];
        float x2 = xr[(size_t)(1024+j0)*32+b0];
        float x3 = xr[(size_t)(1536+j0)*32+b0];
        wmma::fragment<wmma::matrix_a,16,16,16,__nv_bfloat16,wmma::row_major> af[2];
        wmma::fragment<wmma::matrix_b,16,16,16,__nv_bfloat16,wmma::row_major> bf;
        wmma::fragment<wmma::accumulator,16,16,16,float> cf[2][2];
        #pragma unroll
        for (int i=0;i<2;i++)
            #pragma unroll
            for (int j=0;j<2;j++) wmma::fill_fragment(cf[i][j], 0.f);
        #pragma unroll
        for (int kt=0;kt<4;kt++){
            int k = w*64 + kt*16;
            #pragma unroll
            for (int mi=0;mi<2;mi++) wmma::load_matrix_sync(af[mi], Aw + (size_t)mi*16*512 + k, 512);
            #pragma unroll
            for (int ni=0;ni<2;ni++){
                wmma::load_matrix_sync(bf, Bh + (size_t)k*32 + ni*16, 32);
                #pragma unroll
                for (int mi=0;mi<2;mi++) wmma::mma_sync(cf[mi][ni], af[mi], bf, cf[mi][ni]);
            }
        }
        #pragma unroll
        for (int mi=0;mi<2;mi++)
            #pragma unroll
            for (int ni=0;ni<2;ni++)
                wmma::store_matrix_sync(&Rs[w][mi*16][ni*16], cf[mi][ni], 32, wmma::mem_row_major);
        __syncthreads();
        {
            float gg[4];
            #pragma unroll
            for (int g=0; g<4; g++){
                float s = 0.f;
                #pragma unroll
                for (int w8=0; w8<8; w8++) s += Rs[w8][g*8+jj0][b0];
                gg[g] = s;
            }
            float gi = sigf (gg[0] + x0);
            float gf = sigf (gg[1] + x1);
            float gc = tanhf(gg[2] + x2);
            float go = sigf (gg[3] + x3);
            size_t ci = ((size_t)dir*512+j0)*32+b0;
            float cn = gf*g_cenc[ci] + gi*gc;
            g_cenc[ci] = cn;
            float hn = go*tanhf(cn);
            size_t ho = (((size_t)(1-par)*2+dir)*512 + j0)*32 + b0;
            g_henc[ho]  = hn;
            g_hencb[ho] = __float2bfloat16(hn);
            int s = dir ? (39-t) : t;
            g_enchb[((size_t)b0*40+s)*1024 + dir*512 + j0] = __float2bfloat16(hn);
        }
        __threadfence();
        __syncthreads();
        if (tid == 0) atomicAdd(&g_ctr_e, 1u);
        if (t < 39) waitctr(&g_ctr_e, (unsigned)(t+1)*128u);
    }
}

__global__ void k_mkcat(){
    int i = blockIdx.x*blockDim.x + threadIdx.x;
    if (i < 32*1024){
        int b = i>>10, k = i&1023; int dir = k>>9, kk = k&511;
        g_hcc[i] = g_henc[(((size_t)0*2+dir)*512 + kk)*32 + b];
        g_ccc[i] = g_cenc[((size_t)dir*512 + kk)*32 + b];
    }
}

// ---------------- persistent fused decoder: 224 blocks, 39 steps ----------------
__global__ void __launch_bounds__(256,2) k_ddec(const float* __restrict__ masks){
    __shared__ float Rs[8][16][32];
    int blk = blockIdx.x, tid = threadIdx.x, w = tid>>5;
    for (int t=0;t<39;t++){
        int par = t&1;
        if (blk < 128){
            if (t > 0){
                waitctr(&g_ctr_d, (unsigned)t*128u);
                waitctr(&g_ctr_c, (unsigned)t*32u);
            }
            int bl = blk;
            // prefetch x gate operands before the wmma mainloop
            int jj = (tid>>5)&3, b = tid&31;
            int j = bl*4 + jj;
            const float* xr = g_xe + (size_t)t*2048*32;
            float x0 = xr[(size_t)(      j)*32+b];
            float x1 = xr[(size_t)( 512+j)*32+b];
            float x2 = xr[(size_t)(1024+j)*32+b];
            float x3 = xr[(size_t)(1536+j)*32+b];
            const __nv_bfloat16* Aw = g_wdrb + (size_t)bl*16*1024;
            const __nv_bfloat16* Bh = g_hcatb + (size_t)par*1024*32;
            wmma::fragment<wmma::matrix_a,16,16,16,__nv_bfloat16,wmma::row_major> af;
            wmma::fragment<wmma::matrix_b,16,16,16,__nv_bfloat16,wmma::row_major> bf;
            wmma::fragment<wmma::accumulator,16,16,16,float> cf[2];
            #pragma unroll
            for (int jq=0;jq<2;jq++) wmma::fill_fragment(cf[jq], 0.f);
            #pragma unroll
            for (int ktl=0;ktl<8;ktl++){
                int k = (w*8 + ktl)*16;
                wmma::load_matrix_sync(af, Aw + k, 1024);
                #pragma unroll
                for (int ni=0;ni<2;ni++){
                    wmma::load_matrix_sync(bf, Bh + (size_t)k*32 + ni*16, 32);
                    wmma::mma_sync(cf[ni], af, bf, cf[ni]);
                }
            }
            #pragma unroll
            for (int ni=0;ni<2;ni++)
                wmma::store_matrix_sync(&Rs[w][0][ni*16], cf[ni], 32, wmma::mem_row_major);
            __syncthreads();
            if (tid < 128){
                float gg[4];
                #pragma unroll
                for (int g=0; g<4; g++){
                    float s = 0.f;
                    #pragma unroll
                    for (int w8=0; w8<8; w8++) s += Rs[w8][g*4+jj][b];
                    gg[g] = s;
                }
                float gi = sigf (gg[0] + x0);
                float gf = sigf (gg[1] + x1);
                float gc = tanhf(gg[2] + x2);
                float go = sigf (gg[3] + x3);
                size_t ci = (size_t)j*32 + b;
                float cn = gf*g_cdec[ci] + gi*gc;
                g_cdec[ci] = cn;
                float hn = go*tanhf(cn);
                __nv_bfloat16 hb = __float2bfloat16(hn);
                g_kcat[ci] = hn;
                g_kcatb[ci] = hb;
                g_hcatb[(size_t)(1-par)*1024*32 + ci] = hb;
            }
            __threadfence();
            __syncthreads();
            if (tid == 0) atomicAdd(&g_ctr_d, 1u);
        } else if (blk < 192){
            int ab = blk - 128, b = ab>>1, half = ab&1;
            int lane = tid&31;
            float* hv = (float*)Rs;
            float* sc = hv + 512;
            waitctr(&g_ctr_d, (unsigned)(t+1)*128u);
            for (int i=tid;i<512;i+=256) hv[i] = g_kcat[(size_t)i*32+b];
            __syncthreads();
            #pragma unroll
            for (int q=0;q<5;q++){
                int s = w*5+q;
                const __nv_bfloat16* ep = g_encpb + ((size_t)b*40+s)*512;
                float p = 0.f;
                for (int k=lane;k<512;k+=32) p += __bfloat162float(ep[k])*hv[k];
                #pragma unroll
                for (int o=16;o;o>>=1) p += __shfl_down_sync(0xffffffffu, p, o);
                if (!lane) sc[s] = (masks[b*40+s] > 0.f) ? -INFINITY : p;
            }
            __syncthreads();
            if (tid == 0){
                float m = -INFINITY;
                for (int s=0;s<40;s++) m = fmaxf(m, sc[s]);
                float sum = 0.f;
                for (int s=0;s<40;s++){ float e = expf(sc[s]-m); sc[s]=e; sum+=e; }
                float inv = 1.f/sum;
                for (int s=0;s<40;s++) sc[s] *= inv;
            }
            __syncthreads();
            for (int jj=tid + half*512; jj<half*512+512; jj+=256){
                float acc = 0.f;
                #pragma unroll 8
                for (int s=0;s<40;s++)
                    acc += sc[s]*__bfloat162float(g_enchb[((size_t)b*40+s)*1024 + jj]);
                g_kcatb[(size_t)(512+jj)*32 + b] = __float2bfloat16(acc);
            }
            __threadfence();
            __syncthreads();
            if (tid == 0) atomicAdd(&g_ctr_a, 1u);
        } else {
            int bl = blk - 192;
            const __nv_bfloat16* Aw = g_wcombb + (size_t)bl*16*1536;
            wmma::fragment<wmma::matrix_a,16,16,16,__nv_bfloat16,wmma::row_major> af;
            wmma::fragment<wmma::matrix_b,16,16,16,__nv_bfloat16,wmma::row_major> bf;
            wmma::fragment<wmma::accumulator,16,16,16,float> cf[2];
            #pragma unroll
            for (int jq=0;jq<2;jq++) wmma::fill_fragment(cf[jq], 0.f);
            waitctr(&g_ctr_d, (unsigned)(t+1)*128u);
            #pragma unroll
            for (int i=0;i<4;i++){
                int k = (w + 8*i)*16;
                wmma::load_matrix_sync(af, Aw + k, 1536);
                #pragma unroll
                for (int ni=0;ni<2;ni++){
                    wmma::load_matrix_sync(bf, g_kcatb + (size_t)k*32 + ni*16, 32);
                    wmma::mma_sync(cf[ni], af, bf, cf[ni]);
                }
            }
            waitctr(&g_ctr_a, (unsigned)(t+1)*64u);
            #pragma unroll
            for (int i=4;i<12;i++){
                int k = (w + 8*i)*16;
                wmma::load_matrix_sync(af, Aw + k, 1536);
                #pragma unroll
                for (int ni=0;ni<2;ni++){
                    wmma::load_matrix_sync(bf, g_kcatb + (size_t)k*32 + ni*16, 32);
                    wmma::mma_sync(cf[ni], af, bf, cf[ni]);
                }
            }
            #pragma unroll
            for (int ni=0;ni<2;ni++)
                wmma::store_matrix_sync(&Rs[w][0][ni*16], cf[ni], 32, wmma::mem_row_major);
            __syncthreads();
            #pragma unroll
            for (int rep=0; rep<2; rep++){
                int idx = tid + rep*256;
                int nloc = idx>>5, b = idx&31;
                float s = 0.f;
                #pragma unroll
                for (int w8=0; w8<8; w8++) s += Rs[w8][nloc][b];
                float v = tanhf(s);
                int n = bl*16 + nloc;
                g_hcatb[(size_t)(1-par)*1024*32 + (size_t)(512+n)*32 + b] = __float2bfloat16(v);
                g_outsb[((size_t)t*32+b)*512 + n] = __float2bfloat16(v);
            }
            __threadfence();
            __syncthreads();
            if (tid == 0) atomicAdd(&g_ctr_c, 1u);
        }
    }
}

// ---------------- final lse combine + output (merged) ----------------
__global__ void k_lse(const int* tgt, float* out){
    int m = blockIdx.x*blockDim.x + threadIdx.x;
    if (m < 1248){
        float mx = -INFINITY, s = 0.f;
        for (int j=0;j<NTILES;j++){
            float pm = g_pmax[(size_t)j*1280 + m], ps = g_psum[(size_t)j*1280 + m];
            if (pm > mx){ s = s*fexp(mx-pm) + ps; mx = pm; }
            else s += ps*fexp(pm-mx);
        }
        float lse = mx + logf(s);
        int tv = tgt[m + 32];
        g_plogp[m] = (tv != 0) ? (g_pick[m] - lse) : 0.f;
    }
    // grid-wide completion then reduce in block 0 is racy; keep separate pass below
}

__global__ void k_out(float* out){
    int b = threadIdx.x;
    if (b < 32){
        float s = 0.f;
        for (int t=0;t<39;t++) s += g_plogp[t*32 + b];
        out[b] = s;
    }
}

// ---------------- launch ----------------
extern "C" void kernel_launch(void* const* d_in, const int* in_sizes, int n_in,
                              void* d_out, int out_size){
    const int*   src   = (const int*)d_in[0];
    const int*   tgt   = (const int*)d_in[1];
    const float* masks = (const float*)d_in[2];
    const float* se    = (const float*)d_in[3];
    const float* te    = (const float*)d_in[4];
    const float* eWif  = (const float*)d_in[5];
    const float* eWhf  = (const float*)d_in[6];
    const float* ebf   = (const float*)d_in[7];
    const float* eWib  = (const float*)d_in[8];
    const float* eWhb  = (const float*)d_in[9];
    const float* ebb   = (const float*)d_in[10];
    const float* dWih  = (const float*)d_in[11];
    const float* dWhh  = (const float*)d_in[12];
    const float* db    = (const float*)d_in[13];
    const float* Wh    = (const float*)d_in[14];
    const float* Wc    = (const float*)d_in[15];
    const float* Watt  = (const float*)d_in[16];
    const float* Wcomb = (const float*)d_in[17];
    const float* Wv    = (const float*)d_in[18];

    __nv_bfloat16 *p_srceb,*p_srcerb,*p_tgteb,*p_wifb,*p_wibb,*p_widb,*p_wattb,*p_enchb,*p_wvb,*p_outsb,*p_hcatb,*p_encpb;
    float *p_xf,*p_xb,*p_xe,*p_hcc,*p_ccc,*p_cdec;
    cudaGetSymbolAddress((void**)&p_srceb,  g_srceb);
    cudaGetSymbolAddress((void**)&p_srcerb, g_srcerb);
    cudaGetSymbolAddress((void**)&p_tgteb,  g_tgteb);
    cudaGetSymbolAddress((void**)&p_wifb,   g_wifb);
    cudaGetSymbolAddress((void**)&p_wibb,   g_wibb);
    cudaGetSymbolAddress((void**)&p_widb,   g_widb);
    cudaGetSymbolAddress((void**)&p_wattb,  g_wattb);
    cudaGetSymbolAddress((void**)&p_enchb,  g_enchb);
    cudaGetSymbolAddress((void**)&p_wvb,    g_wvb);
    cudaGetSymbolAddress((void**)&p_outsb,  g_outsb);
    cudaGetSymbolAddress((void**)&p_hcatb,  g_hcatb);
    cudaGetSymbolAddress((void**)&p_encpb,  g_encpb);
    cudaGetSymbolAddress((void**)&p_xf,     g_xf);
    cudaGetSymbolAddress((void**)&p_xb,     g_xb);
    cudaGetSymbolAddress((void**)&p_xe,     g_xe);
    cudaGetSymbolAddress((void**)&p_hcc,    g_hcc);
    cudaGetSymbolAddress((void**)&p_ccc,    g_ccc);
    cudaGetSymbolAddress((void**)&p_cdec,   g_cdec);

    const int SM_GEMM = 3*2*128*72*2;   // 110592
    cudaFuncSetAttribute(k_bgemm<0>, cudaFuncAttributeMaxDynamicSharedMemorySize, SM_GEMM);
    cudaFuncSetAttribute(k_bgemm<1>, cudaFuncAttributeMaxDynamicSharedMemorySize, SM_GEMM);
    cudaFuncSetAttribute(k_bgemm<2>, cudaFuncAttributeMaxDynamicSharedMemorySize, SM_GEMM);

    k_gather<<<512,256>>>(src, tgt, se, te);
    k_prep<<<1024,256>>>(dWih, dWhh, eWif, eWib, eWhf, eWhb, Watt, Wcomb);
    k_wvb<<<2048,256>>>(Wv);
    k_bgemm<1><<<dim3(16,10),256,SM_GEMM>>>(p_srceb,  p_wifb, ebf, p_xf, 2048, 256, nullptr);
    k_bgemm<1><<<dim3(16,10),256,SM_GEMM>>>(p_srcerb, p_wibb, ebb, p_xb, 2048, 256, nullptr);

    k_enc_all<<<128,256>>>();

    k_bgemm<1><<<dim3(16,10),256,SM_GEMM>>>(p_tgteb, p_widb, db, p_xe, 2048, 256, nullptr);

    k_mkcat<<<128,256>>>();
    k_gemm<<<dim3(1,8),256>>>(p_hcc, 1024, Wh, 1024, nullptr, p_hcatb, 32, 512, 1024);
    k_gemm<<<dim3(1,8),256>>>(p_ccc, 1024, Wc, 1024, p_cdec, nullptr, 32, 512, 1024);
    k_bgemm<0><<<dim3(4,10),256,SM_GEMM>>>(p_enchb, p_wattb, nullptr, (float*)p_encpb, 512, 1024, nullptr);

    k_ddec<<<224,256>>>(masks);

    k_bgemm<2><<<dim3(NTILES,10),256,SM_GEMM>>>(p_outsb, p_wvb, nullptr, nullptr, 50048, 512, tgt);
    k_lse<<<10,128>>>(tgt, (float*)d_out);
    k_out<<<1,32>>>((float*)d_out);
}

// round 17
// speedup vs baseline: 1.1436x; 1.0354x over previous
#include <cuda_runtime.h>
#include <cuda_bf16.h>
#include <mma.h>
#include <math.h>
#include <stdint.h>

using namespace nvcuda;

// S=40, B=32, T=40, E=256, H=512, V=50000; decoder rows 1248 (pad 1280)
#define NTILES 391

#define CPA16(sdst, gsrc) asm volatile("cp.async.cg.shared.global [%0], [%1], 16;\n" :: "r"(sdst), "l"(gsrc))
#define CPCOMMIT() asm volatile("cp.async.commit_group;\n" ::: "memory")
#define CPWAIT1() asm volatile("cp.async.wait_group 1;\n" ::: "memory")
#define CPWAIT0() asm volatile("cp.async.wait_group 0;\n" ::: "memory")

// ---------------- static device scratch ----------------
__device__ __nv_bfloat16 g_srceb [1280*256];
__device__ __nv_bfloat16 g_srcerb[1280*256];
__device__ __nv_bfloat16 g_tgteb [1280*256];
__device__ __nv_bfloat16 g_wifb  [2048*256];
__device__ __nv_bfloat16 g_wibb  [2048*256];
__device__ __nv_bfloat16 g_widb  [2048*256];
__device__ __nv_bfloat16 g_wattb [512*1024];
__device__ __nv_bfloat16 g_wencb [2*2048*512];   // [dir][2048perm][512]
__device__ __nv_bfloat16 g_wdrb  [2048*1024];    // [2048perm][1024]
__device__ __nv_bfloat16 g_wcombb[512*1536];
__device__ float g_xf   [40*2048*32];   // [t][2048][32]
__device__ float g_xb   [40*2048*32];
__device__ float g_xe   [40*2048*32];
__device__ float g_henc [2*2*512*32];
__device__ __nv_bfloat16 g_hencb[2*2*512*32];
__device__ float g_cenc [2*512*32];
__device__ __nv_bfloat16 g_enchb[1280*1024];
__device__ __nv_bfloat16 g_encpb[1280*512];
__device__ float g_hcc  [32*1024];
__device__ float g_ccc  [32*1024];
__device__ __nv_bfloat16 g_hcatb[2*1024*32];
__device__ float g_cdec [512*32];
__device__ float g_kcat [512*32];
__device__ __nv_bfloat16 g_kcatb[1536*32];
__device__ __nv_bfloat16 g_outsb[1280*512];
__device__ __nv_bfloat16 g_wvb  [50048ull*512];
__device__ float g_pmax [NTILES*1280];
__device__ float g_psum [NTILES*1280];
__device__ float g_pick [1248];
__device__ float g_plogp[1248];
// phase counters (zeroed in k_prep each exec)
__device__ unsigned g_ctr_d;
__device__ unsigned g_ctr_a;
__device__ unsigned g_ctr_c;
__device__ unsigned g_ctr_e;

__device__ __forceinline__ float sigf(float x){ return 1.f/(1.f+expf(-x)); }

__device__ __forceinline__ float fexp(float x){
    float z = fmaxf(x * 1.44269504089f, -100.f);
    float zf = z + 12582912.f;
    int   k  = __float_as_int(zf) - 0x4B400000;
    float r  = z - (zf - 12582912.f);
    float p  = 1.33335581e-3f;
    p = p*r + 9.61812910e-3f;
    p = p*r + 5.55041087e-2f;
    p = p*r + 2.40226507e-1f;
    p = p*r + 6.93147181e-1f;
    p = p*r + 1.0f;
    return __int_as_float(__float_as_int(p) + (k << 23));
}

__device__ __forceinline__ void waitctr(unsigned* c, unsigned tgt){
    if (threadIdx.x == 0){
        while (atomicAdd(c, 0u) < tgt) { }
    }
    __syncthreads();
    __threadfence();
}

// ---------------- prep ----------------
__global__ void k_prep(const float* dWih, const float* dWhh, const float* eWif,
                       const float* eWib, const float* eWhf, const float* eWhb,
                       const float* Watt, const float* Wcomb){
    size_t stride = (size_t)gridDim.x*blockDim.x;
    size_t id0 = (size_t)blockIdx.x*blockDim.x + threadIdx.x;
    if (id0 == 0){ g_ctr_d = 0u; g_ctr_a = 0u; g_ctr_c = 0u; g_ctr_e = 0u; }
    for (size_t i=id0; i<2048ull*1024; i+=stride){
        int r=(int)(i>>10), k=(int)(i&1023);
        int bl=r>>4, loc=r&15, g=loc>>2, jj=loc&3;
        int n = g*512 + bl*4 + jj;
        float v = (k<512) ? dWhh[(size_t)n*512+k] : dWih[(size_t)n*768 + 256 + (k-512)];
        g_wdrb[i] = __float2bfloat16(v);
    }
    for (size_t i=id0; i<2048ull*512; i+=stride){
        int r=(int)(i>>9), k=(int)(i&511);
        int nb=r>>5, loc=r&31, g=loc>>3, jj=loc&7;
        int n = g*512 + nb*8 + jj;
        g_wencb[i]               = __float2bfloat16(eWhf[(size_t)n*512+k]);
        g_wencb[2048ull*512 + i] = __float2bfloat16(eWhb[(size_t)n*512+k]);
    }
    for (size_t i=id0; i<512ull*1536; i+=stride) g_wcombb[i] = __float2bfloat16(Wcomb[i]);
    for (size_t i=id0; i<2048ull*256; i+=stride){
        int n=(int)(i>>8), k=(int)(i&255);
        g_wifb[i] = __float2bfloat16(eWif[i]);
        g_wibb[i] = __float2bfloat16(eWib[i]);
        g_widb[i] = __float2bfloat16(dWih[(size_t)n*768 + k]);
    }
    for (size_t i=id0; i<512ull*1024; i+=stride) g_wattb[i] = __float2bfloat16(Watt[i]);
    for (size_t i=id0; i<2ull*2*512*32; i+=stride){ g_henc[i]=0.f; g_hencb[i]=__float2bfloat16(0.f); }
    for (size_t i=id0; i<2ull*512*32;   i+=stride) g_cenc[i]=0.f;
    for (size_t i=id0; i<512ull*32;     i+=stride) g_cdec[i]=0.f;
    for (size_t i=id0; i<2ull*1024*32;  i+=stride) g_hcatb[i]=__float2bfloat16(0.f);
    for (size_t i=id0; i<32ull*512;     i+=stride) g_outsb[1248ull*512+i]=__float2bfloat16(0.f);
    for (size_t i=id0; i<32ull*256;     i+=stride) g_tgteb[1248ull*256+i]=__float2bfloat16(0.f);
}

__global__ void k_wvb(const float* Wv){
    size_t stride = (size_t)gridDim.x*blockDim.x;
    size_t tot = 50048ull*512/2;
    for (size_t i=(size_t)blockIdx.x*blockDim.x+threadIdx.x; i<tot; i+=stride){
        size_t v = (i*2) >> 9;
        float2 x = (v<50000) ? ((const float2*)Wv)[i] : make_float2(0.f,0.f);
        ((__nv_bfloat162*)g_wvb)[i] = __floats2bfloat162_rn(x.x, x.y);
    }
}

__global__ void k_gather(const int* src, const int* tgt, const float* se, const float* te){
    size_t stride = (size_t)gridDim.x*blockDim.x;
    for (size_t i=(size_t)blockIdx.x*blockDim.x+threadIdx.x; i<(size_t)(1280+1280+1248)*256; i+=stride){
        int k=(int)(i&255); size_t m=i>>8;
        if (m<1280) g_srceb[m*256+k]=__float2bfloat16(se[(size_t)src[m]*256+k]);
        else if (m<2560){
            size_t mm=m-1280; int tt=(int)(mm>>5), bb=(int)(mm&31);
            g_srcerb[mm*256+k]=__float2bfloat16(se[(size_t)src[(39-tt)*32+bb]*256+k]);
        } else {
            size_t mm=m-2560;
            g_tgteb[mm*256+k]=__float2bfloat16(te[(size_t)tgt[mm]*256+k]);
        }
    }
}

// ---------------- 3-stage pipelined bf16 wmma GEMM: C[M][N]=A[M][K]@B[N][K]^T ----------------
// MODE 0: bf16 out | MODE 1: x layout fp32
template<int MODE>
__global__ void __launch_bounds__(256) k_bgemm(const __nv_bfloat16* __restrict__ A,
        const __nv_bfloat16* __restrict__ B, const float* __restrict__ bias,
        float* __restrict__ C, int N, int K){
    extern __shared__ char sm[];
    const int LD = 72;
    __nv_bfloat16* As = (__nv_bfloat16*)sm;
    __nv_bfloat16* Bs = (__nv_bfloat16*)(sm + 3*128*LD*2);
    float* scr = (float*)sm;
    int n0 = blockIdx.x*128, m0 = blockIdx.y*128;
    int tid = threadIdx.x, wp = tid>>5, wm = wp>>2, wn = wp&3;
    wmma::fragment<wmma::matrix_a,16,16,16,__nv_bfloat16,wmma::row_major> af[4];
    wmma::fragment<wmma::matrix_b,16,16,16,__nv_bfloat16,wmma::col_major> bf2[2];
    wmma::fragment<wmma::accumulator,16,16,16,float> cf[4][2];
    #pragma unroll
    for (int i=0;i<4;i++)
        #pragma unroll
        for (int j=0;j<2;j++) wmma::fill_fragment(cf[i][j], 0.f);
    int nch = K>>6;
    int row = tid>>3, seg = tid&7;
    auto issue = [&](int c, int st){
        #pragma unroll
        for (int i=0;i<4;i++){
            int r = row + i*32;
            const __nv_bfloat16* ga = A + (size_t)(m0+r)*K + c*64 + seg*8;
            unsigned sa = (unsigned)__cvta_generic_to_shared(As + (st*128+r)*LD + seg*8);
            CPA16(sa, ga);
            const __nv_bfloat16* gb = B + (size_t)(n0+r)*K + c*64 + seg*8;
            unsigned sb = (unsigned)__cvta_generic_to_shared(Bs + (st*128+r)*LD + seg*8);
            CPA16(sb, gb);
        }
    };
    issue(0,0); CPCOMMIT();
    if (nch > 1){ issue(1,1); CPCOMMIT(); }
    int s3 = 2;
    for (int c=0;c<nch;c++){
        if (c+1<nch) CPWAIT1(); else CPWAIT0();
        __syncthreads();
        if (c+2<nch){ issue(c+2, s3); CPCOMMIT(); s3 = (s3==2)?0:(s3+1); }
        int st = c - (c/3)*3;
        #pragma unroll
        for (int ks=0;ks<4;ks++){
            #pragma unroll
            for (int i=0;i<4;i++)
                wmma::load_matrix_sync(af[i], As + (size_t)(st*128 + wm*64 + i*16)*LD + ks*16, LD);
            #pragma unroll
            for (int j=0;j<2;j++)
                wmma::load_matrix_sync(bf2[j], Bs + (size_t)(st*128 + wn*32 + j*16)*LD + ks*16, LD);
            #pragma unroll
            for (int i=0;i<4;i++)
                #pragma unroll
                for (int j=0;j<2;j++) wmma::mma_sync(cf[i][j], af[i], bf2[j], cf[i][j]);
        }
    }
    __syncthreads();
    #pragma unroll
    for (int i=0;i<4;i++)
        #pragma unroll
        for (int j=0;j<2;j++)
            wmma::store_matrix_sync(&scr[(wm*64+i*16)*132 + wn*32 + j*16], cf[i][j], 132, wmma::mem_row_major);
    __syncthreads();
    if (MODE == 1){
        int mg0 = m0 >> 5;
        #pragma unroll
        for (int it=0; it<16; it++){
            int idx = tid + it*256;
            int g = idx >> 10;
            int n = (idx >> 3) & 127;
            int q = idx & 7;
            float bsv = bias ? bias[n0+n] : 0.f;
            float4 v;
            v.x = scr[(g*32 + q*4 + 0)*132 + n] + bsv;
            v.y = scr[(g*32 + q*4 + 1)*132 + n] + bsv;
            v.z = scr[(g*32 + q*4 + 2)*132 + n] + bsv;
            v.w = scr[(g*32 + q*4 + 3)*132 + n] + bsv;
            *(float4*)&C[(((size_t)(mg0+g))*N + (n0+n))*32 + q*4] = v;
        }
    } else {
        __nv_bfloat16* Cb = (__nv_bfloat16*)C;
        for (int idx=tid; idx<128*128; idx+=256){
            int r=idx>>7, cc=idx&127;
            float v = scr[r*132+cc] + (bias ? bias[n0+cc] : 0.f);
            Cb[(size_t)(m0+r)*N + n0+cc] = __float2bfloat16(v);
        }
    }
}

// ---------------- fp32 GEMM transposed-out (decoder init projections) ----------------
__global__ void __launch_bounds__(256) k_gemm(const float* A, int lda, const float* W, int ldw,
        float* C, __nv_bfloat16* Cb, int M, int N, int K){
    int m0 = blockIdx.x*64, n0 = blockIdx.y*64;
    int tid = threadIdx.x, tx = tid&15, ty = tid>>4;
    __shared__ float As[64][33], Bs[64][33];
    float acc[4][4] = {};
    for (int k0=0;k0<K;k0+=32){
        #pragma unroll
        for (int p=0;p<8;p++){
            int idx=tid+p*256; int r=idx>>5, kk=idx&31;
            As[r][kk] = (m0+r<M) ? A[(size_t)(m0+r)*lda+k0+kk] : 0.f;
            Bs[r][kk] = (n0+r<N) ? W[(size_t)(n0+r)*ldw+k0+kk] : 0.f;
        }
        __syncthreads();
        #pragma unroll
        for (int kk=0;kk<32;kk++){
            float av[4], bv[4];
            #pragma unroll
            for (int i=0;i<4;i++) av[i]=As[ty*4+i][kk];
            #pragma unroll
            for (int j=0;j<4;j++) bv[j]=Bs[tx*4+j][kk];
            #pragma unroll
            for (int i=0;i<4;i++)
                #pragma unroll
                for (int j=0;j<4;j++) acc[i][j]+=av[i]*bv[j];
        }
        __syncthreads();
    }
    #pragma unroll
    for (int i=0;i<4;i++){
        int m=m0+ty*4+i; if (m>=M) continue;
        #pragma unroll
        for (int j=0;j<4;j++){
            int n=n0+tx*4+j; if (n>=N) continue;
            if (C)  C [(size_t)n*32 + m] = acc[i][j];
            if (Cb) Cb[(size_t)n*32 + m] = __float2bfloat16(acc[i][j]);
        }
    }
}

// ---------------- persistent encoder: 128 blocks, 40 steps, counter barrier ----------------
__global__ void __launch_bounds__(256,2) k_enc_all(){
    __shared__ float Rs[8][32][32];
    int blk = blockIdx.x, tid = threadIdx.x, w = tid>>5;
    int dir = blk>>6, nb = blk&63;
    const __nv_bfloat16* Aw = g_wencb + ((size_t)dir*2048 + nb*32)*512;
    int jj0 = tid>>5, b0 = tid&31;
    int j0 = nb*8 + jj0;
    const float* xbase = dir ? g_xb : g_xf;
    for (int t=0;t<40;t++){
        int par = t&1;
        const __nv_bfloat16* Bh = g_hencb + (size_t)(par*2+dir)*512*32;
        const float* xr = xbase + (size_t)t*2048*32;
        float x0 = xr[(size_t)(      j0)*32+b0];
        float x1 = xr[(size_t)( 512+j0)*32+b0];
        float x2 = xr[(size_t)(1024+j0)*32+b0];
        float x3 = xr[(size_t)(1536+j0)*32+b0];
        wmma::fragment<wmma::matrix_a,16,16,16,__nv_bfloat16,wmma::row_major> af[2];
        wmma::fragment<wmma::matrix_b,16,16,16,__nv_bfloat16,wmma::row_major> bf;
        wmma::fragment<wmma::accumulator,16,16,16,float> cf[2][2];
        #pragma unroll
        for (int i=0;i<2;i++)
            #pragma unroll
            for (int j=0;j<2;j++) wmma::fill_fragment(cf[i][j], 0.f);
        #pragma unroll
        for (int kt=0;kt<4;kt++){
            int k = w*64 + kt*16;
            #pragma unroll
            for (int mi=0;mi<2;mi++) wmma::load_matrix_sync(af[mi], Aw + (size_t)mi*16*512 + k, 512);
            #pragma unroll
            for (int ni=0;ni<2;ni++){
                wmma::load_matrix_sync(bf, Bh + (size_t)k*32 + ni*16, 32);
                #pragma unroll
                for (int mi=0;mi<2;mi++) wmma::mma_sync(cf[mi][ni], af[mi], bf, cf[mi][ni]);
            }
        }
        #pragma unroll
        for (int mi=0;mi<2;mi++)
            #pragma unroll
            for (int ni=0;ni<2;ni++)
                wmma::store_matrix_sync(&Rs[w][mi*16][ni*16], cf[mi][ni], 32, wmma::mem_row_major);
        __syncthreads();
        {
            float gg[4];
            #pragma unroll
            for (int g=0; g<4; g++){
                float s = 0.f;
                #pragma unroll
                for (int w8=0; w8<8; w8++) s += Rs[w8][g*8+jj0][b0];
                gg[g] = s;
            }
            float gi = sigf (gg[0] + x0);
            float gf = sigf (gg[1] + x1);
            float gc = tanhf(gg[2] + x2);
            float go = sigf (gg[3] + x3);
            size_t ci = ((size_t)dir*512+j0)*32+b0;
            float cn = gf*g_cenc[ci] + gi*gc;
            g_cenc[ci] = cn;
            float hn = go*tanhf(cn);
            size_t ho = (((size_t)(1-par)*2+dir)*512 + j0)*32 + b0;
            g_henc[ho]  = hn;
            g_hencb[ho] = __float2bfloat16(hn);
            int s = dir ? (39-t) : t;
            g_enchb[((size_t)b0*40+s)*1024 + dir*512 + j0] = __float2bfloat16(hn);
        }
        __threadfence();
        __syncthreads();
        if (tid == 0) atomicAdd(&g_ctr_e, 1u);
        if (t < 39) waitctr(&g_ctr_e, (unsigned)(t+1)*128u);
    }
}

__global__ void k_mkcat(){
    int i = blockIdx.x*blockDim.x + threadIdx.x;
    if (i < 32*1024){
        int b = i>>10, k = i&1023; int dir = k>>9, kk = k&511;
        g_hcc[i] = g_henc[(((size_t)0*2+dir)*512 + kk)*32 + b];
        g_ccc[i] = g_cenc[((size_t)dir*512 + kk)*32 + b];
    }
}

// ---------------- MERGED persistent decoder + overlapped vocab GEMM ----------------
// blocks 0..127: dgates | 128..191: att | 192..223: comb | 224..4133: vocab tiles
__global__ void __launch_bounds__(256,2) k_ddec(const float* __restrict__ masks,
                                                const int* __restrict__ tgt){
    extern __shared__ char dsm[];
    int blk = blockIdx.x, tid = threadIdx.x, w = tid>>5;
    if (blk >= 224){
        // ---------- vocab tile: wait for outsb rows, then GEMM + fused lse ----------
        int vb = blk - 224;
        int mt = vb / NTILES, j = vb - mt*NTILES;
        unsigned thr = (unsigned)((mt<9) ? (4*mt+4) : 39) * 32u;
        waitctr(&g_ctr_c, thr);
        const int LD = 72;
        __nv_bfloat16* As = (__nv_bfloat16*)dsm;
        __nv_bfloat16* Bs = (__nv_bfloat16*)(dsm + 3*128*LD*2);
        float* scr = (float*)dsm;
        int n0 = j*128, m0 = mt*128;
        int wp = tid>>5, wm = wp>>2, wn = wp&3;
        wmma::fragment<wmma::matrix_a,16,16,16,__nv_bfloat16,wmma::row_major> af[4];
        wmma::fragment<wmma::matrix_b,16,16,16,__nv_bfloat16,wmma::col_major> bf2[2];
        wmma::fragment<wmma::accumulator,16,16,16,float> cf[4][2];
        #pragma unroll
        for (int i=0;i<4;i++)
            #pragma unroll
            for (int jq=0;jq<2;jq++) wmma::fill_fragment(cf[i][jq], 0.f);
        int row = tid>>3, seg = tid&7;
        auto issue = [&](int c, int st){
            #pragma unroll
            for (int i=0;i<4;i++){
                int r = row + i*32;
                const __nv_bfloat16* ga = g_outsb + (size_t)(m0+r)*512 + c*64 + seg*8;
                unsigned sa = (unsigned)__cvta_generic_to_shared(As + (st*128+r)*LD + seg*8);
                CPA16(sa, ga);
                const __nv_bfloat16* gb = g_wvb + (size_t)(n0+r)*512 + c*64 + seg*8;
                unsigned sb = (unsigned)__cvta_generic_to_shared(Bs + (st*128+r)*LD + seg*8);
                CPA16(sb, gb);
            }
        };
        issue(0,0); CPCOMMIT();
        issue(1,1); CPCOMMIT();
        int s3 = 2;
        for (int c=0;c<8;c++){
            if (c+1<8) CPWAIT1(); else CPWAIT0();
            __syncthreads();
            if (c+2<8){ issue(c+2, s3); CPCOMMIT(); s3 = (s3==2)?0:(s3+1); }
            int st = c - (c/3)*3;
            #pragma unroll
            for (int ks=0;ks<4;ks++){
                #pragma unroll
                for (int i=0;i<4;i++)
                    wmma::load_matrix_sync(af[i], As + (size_t)(st*128 + wm*64 + i*16)*LD + ks*16, LD);
                #pragma unroll
                for (int jq=0;jq<2;jq++)
                    wmma::load_matrix_sync(bf2[jq], Bs + (size_t)(st*128 + wn*32 + jq*16)*LD + ks*16, LD);
                #pragma unroll
                for (int i=0;i<4;i++)
                    #pragma unroll
                    for (int jq=0;jq<2;jq++) wmma::mma_sync(cf[i][jq], af[i], bf2[jq], cf[i][jq]);
            }
        }
        __syncthreads();
        #pragma unroll
        for (int i=0;i<4;i++)
            #pragma unroll
            for (int jq=0;jq<2;jq++)
                wmma::store_matrix_sync(&scr[(wm*64+i*16)*132 + wn*32 + jq*16], cf[i][jq], 132, wmma::mem_row_major);
        __syncthreads();
        {
            int r = tid>>1, hh = tid&1;
            int m = m0 + r;
            if (m < 1248){
                int valid = min(128, 50000 - n0);
                int c0 = hh*64, c1 = min(c0+64, valid);
                float mx = -INFINITY, s = 0.f;
                for (int cc=c0; cc<c1; cc++) mx = fmaxf(mx, scr[r*132+cc]);
                for (int cc=c0; cc<c1; cc++) s += fexp(scr[r*132+cc]-mx);
                float mo = __shfl_xor_sync(0xffffffffu, mx, 1);
                float so = __shfl_xor_sync(0xffffffffu, s, 1);
                float M = fmaxf(mx, mo);
                float S = ((mx == -INFINITY) ? 0.f : s*fexp(mx-M)) +
                          ((mo == -INFINITY) ? 0.f : so*fexp(mo-M));
                if (hh == 0){
                    g_pmax[(size_t)j*1280 + m] = M;
                    g_psum[(size_t)j*1280 + m] = S;
                }
                int tv = tgt[m + 32];
                int lv = tv - n0;
                if (lv >= c0 && lv < c1) g_pick[m] = scr[r*132 + lv];
            }
        }
        return;
    }
    // ---------- decoder roles (R16 logic) ----------
    float* Rs = (float*)dsm;   // [8][16][32]
    for (int t=0;t<39;t++){
        int par = t&1;
        if (blk < 128){
            if (t > 0){
                waitctr(&g_ctr_d, (unsigned)t*128u);
                waitctr(&g_ctr_c, (unsigned)t*32u);
            }
            int bl = blk;
            int jj = (tid>>5)&3, b = tid&31;
            int j = bl*4 + jj;
            const float* xr = g_xe + (size_t)t*2048*32;
            float x0 = xr[(size_t)(      j)*32+b];
            float x1 = xr[(size_t)( 512+j)*32+b];
            float x2 = xr[(size_t)(1024+j)*32+b];
            float x3 = xr[(size_t)(1536+j)*32+b];
            const __nv_bfloat16* Aw = g_wdrb + (size_t)bl*16*1024;
            const __nv_bfloat16* Bh = g_hcatb + (size_t)par*1024*32;
            wmma::fragment<wmma::matrix_a,16,16,16,__nv_bfloat16,wmma::row_major> af;
            wmma::fragment<wmma::matrix_b,16,16,16,__nv_bfloat16,wmma::row_major> bf;
            wmma::fragment<wmma::accumulator,16,16,16,float> cf[2];
            #pragma unroll
            for (int jq=0;jq<2;jq++) wmma::fill_fragment(cf[jq], 0.f);
            #pragma unroll
            for (int ktl=0;ktl<8;ktl++){
                int k = (w*8 + ktl)*16;
                wmma::load_matrix_sync(af, Aw + k, 1024);
                #pragma unroll
                for (int ni=0;ni<2;ni++){
                    wmma::load_matrix_sync(bf, Bh + (size_t)k*32 + ni*16, 32);
                    wmma::mma_sync(cf[ni], af, bf, cf[ni]);
                }
            }
            #pragma unroll
            for (int ni=0;ni<2;ni++)
                wmma::store_matrix_sync(&Rs[(w*16)*32 + ni*16], cf[ni], 32, wmma::mem_row_major);
            __syncthreads();
            if (tid < 128){
                float gg[4];
                #pragma unroll
                for (int g=0; g<4; g++){
                    float s = 0.f;
                    #pragma unroll
                    for (int w8=0; w8<8; w8++) s += Rs[(w8*16 + g*4+jj)*32 + b];
                    gg[g] = s;
                }
                float gi = sigf (gg[0] + x0);
                float gf = sigf (gg[1] + x1);
                float gc = tanhf(gg[2] + x2);
                float go = sigf (gg[3] + x3);
                size_t ci = (size_t)j*32 + b;
                float cn = gf*g_cdec[ci] + gi*gc;
                g_cdec[ci] = cn;
                float hn = go*tanhf(cn);
                __nv_bfloat16 hb = __float2bfloat16(hn);
                g_kcat[ci] = hn;
                g_kcatb[ci] = hb;
                g_hcatb[(size_t)(1-par)*1024*32 + ci] = hb;
            }
            __threadfence();
            __syncthreads();
            if (tid == 0) atomicAdd(&g_ctr_d, 1u);
        } else if (blk < 192){
            int ab = blk - 128, b = ab>>1, half = ab&1;
            int lane = tid&31;
            float* hv = Rs;
            float* sc = hv + 512;
            waitctr(&g_ctr_d, (unsigned)(t+1)*128u);
            for (int i=tid;i<512;i+=256) hv[i] = g_kcat[(size_t)i*32+b];
            __syncthreads();
            #pragma unroll
            for (int q=0;q<5;q++){
                int s = w*5+q;
                const __nv_bfloat16* ep = g_encpb + ((size_t)b*40+s)*512;
                float p = 0.f;
                for (int k=lane;k<512;k+=32) p += __bfloat162float(ep[k])*hv[k];
                #pragma unroll
                for (int o=16;o;o>>=1) p += __shfl_down_sync(0xffffffffu, p, o);
                if (!lane) sc[s] = (masks[b*40+s] > 0.f) ? -INFINITY : p;
            }
            __syncthreads();
            if (tid == 0){
                float m = -INFINITY;
                for (int s=0;s<40;s++) m = fmaxf(m, sc[s]);
                float sum = 0.f;
                for (int s=0;s<40;s++){ float e = expf(sc[s]-m); sc[s]=e; sum+=e; }
                float inv = 1.f/sum;
                for (int s=0;s<40;s++) sc[s] *= inv;
            }
            __syncthreads();
            for (int jj=tid + half*512; jj<half*512+512; jj+=256){
                float acc = 0.f;
                #pragma unroll 8
                for (int s=0;s<40;s++)
                    acc += sc[s]*__bfloat162float(g_enchb[((size_t)b*40+s)*1024 + jj]);
                g_kcatb[(size_t)(512+jj)*32 + b] = __float2bfloat16(acc);
            }
            __threadfence();
            __syncthreads();
            if (tid == 0) atomicAdd(&g_ctr_a, 1u);
        } else {
            int bl = blk - 192;
            const __nv_bfloat16* Aw = g_wcombb + (size_t)bl*16*1536;
            wmma::fragment<wmma::matrix_a,16,16,16,__nv_bfloat16,wmma::row_major> af;
            wmma::fragment<wmma::matrix_b,16,16,16,__nv_bfloat16,wmma::row_major> bf;
            wmma::fragment<wmma::accumulator,16,16,16,float> cf[2];
            #pragma unroll
            for (int jq=0;jq<2;jq++) wmma::fill_fragment(cf[jq], 0.f);
            waitctr(&g_ctr_d, (unsigned)(t+1)*128u);
            #pragma unroll
            for (int i=0;i<4;i++){
                int k = (w + 8*i)*16;
                wmma::load_matrix_sync(af, Aw + k, 1536);
                #pragma unroll
                for (int ni=0;ni<2;ni++){
                    wmma::load_matrix_sync(bf, g_kcatb + (size_t)k*32 + ni*16, 32);
                    wmma::mma_sync(cf[ni], af, bf, cf[ni]);
                }
            }
            waitctr(&g_ctr_a, (unsigned)(t+1)*64u);
            #pragma unroll
            for (int i=4;i<12;i++){
                int k = (w + 8*i)*16;
                wmma::load_matrix_sync(af, Aw + k, 1536);
                #pragma unroll
                for (int ni=0;ni<2;ni++){
                    wmma::load_matrix_sync(bf, g_kcatb + (size_t)k*32 + ni*16, 32);
                    wmma::mma_sync(cf[ni], af, bf, cf[ni]);
                }
            }
            #pragma unroll
            for (int ni=0;ni<2;ni++)
                wmma::store_matrix_sync(&Rs[(w*16)*32 + ni*16], cf[ni], 32, wmma::mem_row_major);
            __syncthreads();
            #pragma unroll
            for (int rep=0; rep<2; rep++){
                int idx = tid + rep*256;
                int nloc = idx>>5, b = idx&31;
                float s = 0.f;
                #pragma unroll
                for (int w8=0; w8<8; w8++) s += Rs[(w8*16 + nloc)*32 + b];
                float v = tanhf(s);
                int n = bl*16 + nloc;
                g_hcatb[(size_t)(1-par)*1024*32 + (size_t)(512+n)*32 + b] = __float2bfloat16(v);
                g_outsb[((size_t)t*32+b)*512 + n] = __float2bfloat16(v);
            }
            __threadfence();
            __syncthreads();
            if (tid == 0) atomicAdd(&g_ctr_c, 1u);
        }
    }
}

// ---------------- final lse combine + output ----------------
__global__ void k_lse(const int* tgt){
    int m = blockIdx.x*blockDim.x + threadIdx.x;
    if (m >= 1248) return;
    float mx = -INFINITY, s = 0.f;
    for (int j=0;j<NTILES;j++){
        float pm = g_pmax[(size_t)j*1280 + m], ps = g_psum[(size_t)j*1280 + m];
        if (pm > mx){ s = s*fexp(mx-pm) + ps; mx = pm; }
        else s += ps*fexp(pm-mx);
    }
    float lse = mx + logf(s);
    int tv = tgt[m + 32];
    g_plogp[m] = (tv != 0) ? (g_pick[m] - lse) : 0.f;
}

__global__ void k_out(float* out){
    int b = threadIdx.x;
    if (b < 32){
        float s = 0.f;
        for (int t=0;t<39;t++) s += g_plogp[t*32 + b];
        out[b] = s;
    }
}

// ---------------- launch ----------------
extern "C" void kernel_launch(void* const* d_in, const int* in_sizes, int n_in,
                              void* d_out, int out_size){
    const int*   src   = (const int*)d_in[0];
    const int*   tgt   = (const int*)d_in[1];
    const float* masks = (const float*)d_in[2];
    const float* se    = (const float*)d_in[3];
    const float* te    = (const float*)d_in[4];
    const float* eWif  = (const float*)d_in[5];
    const float* eWhf  = (const float*)d_in[6];
    const float* ebf   = (const float*)d_in[7];
    const float* eWib  = (const float*)d_in[8];
    const float* eWhb  = (const float*)d_in[9];
    const float* ebb   = (const float*)d_in[10];
    const float* dWih  = (const float*)d_in[11];
    const float* dWhh  = (const float*)d_in[12];
    const float* db    = (const float*)d_in[13];
    const float* Wh    = (const float*)d_in[14];
    const float* Wc    = (const float*)d_in[15];
    const float* Watt  = (const float*)d_in[16];
    const float* Wcomb = (const float*)d_in[17];
    const float* Wv    = (const float*)d_in[18];

    __nv_bfloat16 *p_srceb,*p_srcerb,*p_tgteb,*p_wifb,*p_wibb,*p_widb,*p_wattb,*p_enchb,*p_encpb,*p_hcatb;
    float *p_xf,*p_xb,*p_xe,*p_hcc,*p_ccc,*p_cdec;
    cudaGetSymbolAddress((void**)&p_srceb,  g_srceb);
    cudaGetSymbolAddress((void**)&p_srcerb, g_srcerb);
    cudaGetSymbolAddress((void**)&p_tgteb,  g_tgteb);
    cudaGetSymbolAddress((void**)&p_wifb,   g_wifb);
    cudaGetSymbolAddress((void**)&p_wibb,   g_wibb);
    cudaGetSymbolAddress((void**)&p_widb,   g_widb);
    cudaGetSymbolAddress((void**)&p_wattb,  g_wattb);
    cudaGetSymbolAddress((void**)&p_enchb,  g_enchb);
    cudaGetSymbolAddress((void**)&p_encpb,  g_encpb);
    cudaGetSymbolAddress((void**)&p_hcatb,  g_hcatb);
    cudaGetSymbolAddress((void**)&p_xf,     g_xf);
    cudaGetSymbolAddress((void**)&p_xb,     g_xb);
    cudaGetSymbolAddress((void**)&p_xe,     g_xe);
    cudaGetSymbolAddress((void**)&p_hcc,    g_hcc);
    cudaGetSymbolAddress((void**)&p_ccc,    g_ccc);
    cudaGetSymbolAddress((void**)&p_cdec,   g_cdec);

    const int SM_GEMM = 3*2*128*72*2;   // 110592
    cudaFuncSetAttribute(k_bgemm<0>, cudaFuncAttributeMaxDynamicSharedMemorySize, SM_GEMM);
    cudaFuncSetAttribute(k_bgemm<1>, cudaFuncAttributeMaxDynamicSharedMemorySize, SM_GEMM);
    cudaFuncSetAttribute(k_ddec,     cudaFuncAttributeMaxDynamicSharedMemorySize, SM_GEMM);

    k_gather<<<512,256>>>(src, tgt, se, te);
    k_prep<<<1024,256>>>(dWih, dWhh, eWif, eWib, eWhf, eWhb, Watt, Wcomb);
    k_wvb<<<2048,256>>>(Wv);
    k_bgemm<1><<<dim3(16,10),256,SM_GEMM>>>(p_srceb,  p_wifb, ebf, p_xf, 2048, 256);
    k_bgemm<1><<<dim3(16,10),256,SM_GEMM>>>(p_srcerb, p_wibb, ebb, p_xb, 2048, 256);

    k_enc_all<<<128,256>>>();

    k_bgemm<1><<<dim3(16,10),256,SM_GEMM>>>(p_tgteb, p_widb, db, p_xe, 2048, 256);

    k_mkcat<<<128,256>>>();
    k_gemm<<<dim3(1,8),256>>>(p_hcc, 1024, Wh, 1024, nullptr, p_hcatb, 32, 512, 1024);
    k_gemm<<<dim3(1,8),256>>>(p_ccc, 1024, Wc, 1024, p_cdec, nullptr, 32, 512, 1024);
    k_bgemm<0><<<dim3(4,10),256,SM_GEMM>>>(p_enchb, p_wattb, nullptr, (float*)p_encpb, 512, 1024);

    // merged decoder + overlapped vocab
    k_ddec<<<224 + 10*NTILES, 256, SM_GEMM>>>(masks, tgt);

    k_lse<<<10,128>>>(tgt);
    k_out<<<1,32>>>((float*)d_out);
}